// round 6
// baseline (speedup 1.0000x reference)
#include <cuda_runtime.h>
#include <math.h>

#define NN 50000
#define EE 800000
#define INF 128
#define HID 256
#define OUTD 40
#define SB 512   // stats blocks

// ---------------- scratch (static device globals; no allocation) -------------
__device__ int    g_deg[NN];
__device__ float  g_dinv[NN];
__device__ int    g_rowptr[NN + 1];
__device__ int    g_cursor[NN];
__device__ int    g_col[EE];
__device__ __align__(16) float g_aggx[(size_t)NN * INF];  // Â x
__device__ __align__(16) float g_m[(size_t)NN * HID];     // conv outputs m1 / m2
__device__ __align__(16) float g_agg[(size_t)NN * HID];   // Â f1(m1)
__device__ __align__(16) float g_p3[(size_t)NN * OUTD];   // dinv * (f2(m2) @ W3)
__device__ __align__(16) float g_h3[(size_t)NN * OUTD];   // conv3 output
__device__ float  g_ps[SB * HID];     // per-block partial sums
__device__ float  g_ps2[SB * HID];    // per-block partial sums of squares
__device__ float  g_scale[HID];
__device__ float  g_shift[HID];

// ---------------- graph preprocessing ----------------------------------------
__global__ void k_init(int n) {
    int i = blockIdx.x * blockDim.x + threadIdx.x;
    if (i < n) g_deg[i] = 1;             // self loop
}

// edge_index is int32 (JAX default x64-disabled): row0 = src, row1 = dst
__global__ void k_deg(const int* __restrict__ ei, int e, int n) {
    int i = blockIdx.x * blockDim.x + threadIdx.x;
    if (i < e) {
        int s = ei[i], d = ei[e + i];
        if ((unsigned)s < (unsigned)n && (unsigned)d < (unsigned)n)
            atomicAdd(&g_deg[d], 1);
    }
}

// single-block scan: dinv, rowptr (exclusive over in-degree), cursor
__global__ void k_scan(int n) {
    __shared__ int warpsums[32];
    __shared__ int s_carry;
    int tid = threadIdx.x;  // 1024
    if (tid == 0) { s_carry = 0; g_rowptr[0] = 0; }
    __syncthreads();
    for (int base = 0; base < n; base += 1024) {
        int i = base + tid;
        int v = 0;
        if (i < n) {
            int d = g_deg[i];
            v = d - 1;
            g_dinv[i] = rsqrtf((float)d);
        }
        int x = v;
        #pragma unroll
        for (int o = 1; o < 32; o <<= 1) {
            int y = __shfl_up_sync(0xFFFFFFFFu, x, o);
            if ((tid & 31) >= o) x += y;
        }
        if ((tid & 31) == 31) warpsums[tid >> 5] = x;
        __syncthreads();
        if (tid < 32) {
            int w = warpsums[tid];
            #pragma unroll
            for (int o = 1; o < 32; o <<= 1) {
                int y = __shfl_up_sync(0xFFFFFFFFu, w, o);
                if (tid >= o) w += y;
            }
            warpsums[tid] = w;
        }
        __syncthreads();
        int incl = x + ((tid >= 32) ? warpsums[(tid >> 5) - 1] : 0) + s_carry;
        if (i < n) { g_rowptr[i + 1] = incl; g_cursor[i] = incl - v; }
        __syncthreads();
        if (tid == 1023) s_carry = incl;
        __syncthreads();
    }
}

__global__ void k_scatter(const int* __restrict__ ei, int e, int n) {
    int i = blockIdx.x * blockDim.x + threadIdx.x;
    if (i < e) {
        int s = ei[i], d = ei[e + i];
        if ((unsigned)s < (unsigned)n && (unsigned)d < (unsigned)n) {
            int pos = atomicAdd(&g_cursor[d], 1);
            if ((unsigned)pos < (unsigned)EE) g_col[pos] = s;
        }
    }
}

// ---------------- aggregation kernels ----------------------------------------
// g_aggx[i] = dinv[i] * ( dinv[i]*x[i] + sum_{s in N(i)} dinv[s]*x[s] )
__global__ void k_aggX(const float* __restrict__ x) {
    int i = blockIdx.x, t = threadIdx.x;  // 128 threads
    float di = g_dinv[i];
    float acc = di * x[(size_t)i * INF + t];
    int e0 = g_rowptr[i], e1 = g_rowptr[i + 1];
    int e = e0;
    for (; e + 1 < e1; e += 2) {
        int s0 = g_col[e], s1 = g_col[e + 1];
        float d0 = g_dinv[s0], d1 = g_dinv[s1];
        float v0 = x[(size_t)s0 * INF + t];
        float v1 = x[(size_t)s1 * INF + t];
        acc += d0 * v0 + d1 * v1;
    }
    if (e < e1) {
        int s = g_col[e];
        acc += g_dinv[s] * x[(size_t)s * INF + t];
    }
    g_aggx[(size_t)i * INF + t] = acc * di;
}

// g_agg[i] = dinv[i] * ( dinv[i]*f(m[i]) + sum dinv[s]*f(m[s]) ), f = relu(affine)
__global__ void k_agg256() {
    int i = blockIdx.x, t = threadIdx.x;  // 256 threads
    const float* __restrict__ m = g_m;
    float sc = g_scale[t], sh = g_shift[t];
    float di = g_dinv[i];
    float acc = di * fmaxf(fmaf(m[(size_t)i * HID + t], sc, sh), 0.f);
    int e0 = g_rowptr[i], e1 = g_rowptr[i + 1];
    int e = e0;
    for (; e + 1 < e1; e += 2) {
        int s0 = g_col[e], s1 = g_col[e + 1];
        float d0 = g_dinv[s0], d1 = g_dinv[s1];
        float v0 = fmaxf(fmaf(m[(size_t)s0 * HID + t], sc, sh), 0.f);
        float v1 = fmaxf(fmaf(m[(size_t)s1 * HID + t], sc, sh), 0.f);
        acc += d0 * v0 + d1 * v1;
    }
    if (e < e1) {
        int s = g_col[e];
        acc += g_dinv[s] * fmaxf(fmaf(m[(size_t)s * HID + t], sc, sh), 0.f);
    }
    g_agg[(size_t)i * HID + t] = acc * di;
}

// g_h3[i] = dinv[i]*(p3[i] + sum p3[s]) + b3   (p3 already has dinv[src] folded)
__global__ void k_agg40(const float* __restrict__ b3) {
    int i = blockIdx.x, t = threadIdx.x;  // 64 threads, 40 active
    if (t >= OUTD) return;
    float acc = g_p3[(size_t)i * OUTD + t];
    int e0 = g_rowptr[i], e1 = g_rowptr[i + 1];
    for (int e = e0; e < e1; e++)
        acc += g_p3[(size_t)g_col[e] * OUTD + t];
    g_h3[(size_t)i * OUTD + t] = acc * g_dinv[i] + b3[t];
}

// ---------------- SGEMM: g_m[M,256] = A[M,K] @ B[K,256] + bias ----------------
// LAYER 1: A = g_aggx (K=128).  LAYER 2: A = g_agg (K=256).
#define BM 128
#define BN 128
#define BK 16
template <int LAYER>
__global__ __launch_bounds__(256) void k_gemm256(
    const float* __restrict__ B, const float* __restrict__ bias, int M) {
    constexpr int K = (LAYER == 1) ? INF : HID;
    const float* __restrict__ A = (LAYER == 1) ? g_aggx : g_agg;
    float* __restrict__ C = g_m;

    __shared__ float As[BK][BM + 4];
    __shared__ float Bs[BK][BN];
    int tid = threadIdx.x;
    int tx = tid & 15, ty = tid >> 4;
    int rowBase = blockIdx.x * BM;
    int colBase = blockIdx.y * BN;
    float acc[8][8];
    #pragma unroll
    for (int i = 0; i < 8; i++)
        #pragma unroll
        for (int j = 0; j < 8; j++) acc[i][j] = 0.f;

    int aRow = tid >> 2;            // 0..63
    int aCol = (tid & 3) << 2;      // 0,4,8,12
    int bRow = tid >> 5;            // 0..7
    int bCol = (tid & 31) << 2;     // 0..124

    for (int kk = 0; kk < K; kk += BK) {
        #pragma unroll
        for (int rr = 0; rr < 2; rr++) {
            int r = rowBase + aRow + rr * 64;
            float4 v = make_float4(0.f, 0.f, 0.f, 0.f);
            if (r < M) v = *(const float4*)(A + (size_t)r * K + kk + aCol);
            As[aCol + 0][aRow + rr * 64] = v.x;
            As[aCol + 1][aRow + rr * 64] = v.y;
            As[aCol + 2][aRow + rr * 64] = v.z;
            As[aCol + 3][aRow + rr * 64] = v.w;
        }
        #pragma unroll
        for (int rr = 0; rr < 2; rr++) {
            int r = kk + bRow + rr * 8;
            *(float4*)&Bs[bRow + rr * 8][bCol] =
                *(const float4*)(B + (size_t)r * 256 + colBase + bCol);
        }
        __syncthreads();
        #pragma unroll
        for (int k = 0; k < BK; k++) {
            float ra[8], rb[8];
            #pragma unroll
            for (int i = 0; i < 8; i++) ra[i] = As[k][ty * 8 + i];
            #pragma unroll
            for (int j = 0; j < 8; j++) rb[j] = Bs[k][tx * 8 + j];
            #pragma unroll
            for (int i = 0; i < 8; i++)
                #pragma unroll
                for (int j = 0; j < 8; j++) acc[i][j] = fmaf(ra[i], rb[j], acc[i][j]);
        }
        __syncthreads();
    }
    int cb = colBase + tx * 8;
    float bv[8];
    #pragma unroll
    for (int j = 0; j < 8; j++) bv[j] = bias[cb + j];
    #pragma unroll
    for (int i = 0; i < 8; i++) {
        int r = rowBase + ty * 8 + i;
        if (r < M) {
            float4 o0 = make_float4(acc[i][0] + bv[0], acc[i][1] + bv[1],
                                    acc[i][2] + bv[2], acc[i][3] + bv[3]);
            float4 o1 = make_float4(acc[i][4] + bv[4], acc[i][5] + bv[5],
                                    acc[i][6] + bv[6], acc[i][7] + bv[7]);
            *(float4*)(C + (size_t)r * 256 + cb)     = o0;
            *(float4*)(C + (size_t)r * 256 + cb + 4) = o1;
        }
    }
}

// ---------------- GEMM: g_p3[M,40] = dinv * ( f2(g_m)[M,256] @ W3[256,40] ) ---
__global__ __launch_bounds__(256) void k_gemm40(
    const float* __restrict__ W, int M) {
    const float* __restrict__ A = g_m;
    __shared__ float As[32][65];
    __shared__ float Ws[32][40];
    __shared__ float ssc[HID], ssh[HID];
    int tid = threadIdx.x;
    ssc[tid] = g_scale[tid];
    ssh[tid] = g_shift[tid];
    __syncthreads();

    int rowBase = blockIdx.x * 64;
    int r = tid & 63;
    int cg = tid >> 6;  // 0..3 -> cols cg*10..cg*10+9
    float acc[10];
    #pragma unroll
    for (int j = 0; j < 10; j++) acc[j] = 0.f;

    int aRow = tid >> 3;        // 0..31
    int aCol = (tid & 7) << 2;  // 0..28

    for (int kk = 0; kk < HID; kk += 32) {
        #pragma unroll
        for (int rr = 0; rr < 2; rr++) {
            int row = rowBase + aRow + rr * 32;
            float4 v = make_float4(0.f, 0.f, 0.f, 0.f);
            if (row < M) v = *(const float4*)(A + (size_t)row * HID + kk + aCol);
            int c = kk + aCol;
            As[aCol + 0][aRow + rr * 32] = fmaxf(fmaf(v.x, ssc[c + 0], ssh[c + 0]), 0.f);
            As[aCol + 1][aRow + rr * 32] = fmaxf(fmaf(v.y, ssc[c + 1], ssh[c + 1]), 0.f);
            As[aCol + 2][aRow + rr * 32] = fmaxf(fmaf(v.z, ssc[c + 2], ssh[c + 2]), 0.f);
            As[aCol + 3][aRow + rr * 32] = fmaxf(fmaf(v.w, ssc[c + 3], ssh[c + 3]), 0.f);
        }
        for (int idx = tid; idx < 32 * OUTD; idx += 256) {
            int kr = idx / OUTD, c = idx % OUTD;
            Ws[kr][c] = W[(size_t)(kk + kr) * OUTD + c];
        }
        __syncthreads();
        #pragma unroll
        for (int k = 0; k < 32; k++) {
            float a = As[k][r];
            #pragma unroll
            for (int j = 0; j < 10; j++)
                acc[j] = fmaf(a, Ws[k][cg * 10 + j], acc[j]);
        }
        __syncthreads();
    }
    int row = rowBase + r;
    if (row < M) {
        float d = g_dinv[row];
        #pragma unroll
        for (int j = 0; j < 10; j++)
            g_p3[(size_t)row * OUTD + cg * 10 + j] = acc[j] * d;
    }
}

// ---------------- BN stats (fp32 block partials, no atomics) -------------------
__global__ void k_stats(int n) {
    int t = threadIdx.x;  // 256
    int b = blockIdx.x;   // SB blocks
    const float* __restrict__ m = g_m;
    float s = 0.f, s2 = 0.f;
    for (int r = b; r < n; r += SB) {
        float v = m[(size_t)r * HID + t];
        s += v;
        s2 = fmaf(v, v, s2);
    }
    g_ps[b * HID + t]  = s;
    g_ps2[b * HID + t] = s2;
}

__global__ void k_bnparams(const float* __restrict__ g, const float* __restrict__ be, int n) {
    int t = threadIdx.x;  // 256
    float s = 0.f, s2 = 0.f;
    #pragma unroll 8
    for (int b = 0; b < SB; b++) {
        s  += g_ps[b * HID + t];
        s2 += g_ps2[b * HID + t];
    }
    float inv_n = 1.f / (float)n;
    float mean = s * inv_n;
    float var  = fmaf(s2, inv_n, -mean * mean);
    float rs = rsqrtf(var + 1e-5f);
    float sc = rs * g[t];
    g_scale[t] = sc;
    g_shift[t] = be[t] - mean * sc;
}

// ---------------- final: out = log_softmax(g_h3 @ Wl + bl) ---------------------
__global__ void k_final(const float* __restrict__ Wl, const float* __restrict__ bl,
                        float* __restrict__ out, int n) {
    __shared__ float sW[OUTD * OUTD];
    __shared__ float sb[OUTD];
    int tid = threadIdx.x;  // 256
    for (int i = tid; i < OUTD * OUTD; i += 256) sW[i] = Wl[i];
    if (tid < OUTD) sb[tid] = bl[tid];
    __syncthreads();
    int warp = tid >> 5, lane = tid & 31;
    int row = blockIdx.x * 8 + warp;
    if (row >= n) return;
    const float* a = g_h3 + (size_t)row * OUTD;
    float a_lo = a[lane];
    float a_hi = (lane < 8) ? a[32 + lane] : 0.f;
    float z0 = sb[lane];
    float z1 = (lane < 8) ? sb[32 + lane] : -1e30f;
    #pragma unroll
    for (int k = 0; k < OUTD; k++) {
        float ak = (k < 32) ? __shfl_sync(0xFFFFFFFFu, a_lo, k)
                            : __shfl_sync(0xFFFFFFFFu, a_hi, k - 32);
        z0 = fmaf(ak, sW[k * OUTD + lane], z0);
        if (lane < 8) z1 = fmaf(ak, sW[k * OUTD + 32 + lane], z1);
    }
    float mx = fmaxf(z0, z1);
    #pragma unroll
    for (int o = 16; o; o >>= 1) mx = fmaxf(mx, __shfl_xor_sync(0xFFFFFFFFu, mx, o));
    float es = expf(z0 - mx) + ((lane < 8) ? expf(z1 - mx) : 0.f);
    #pragma unroll
    for (int o = 16; o; o >>= 1) es += __shfl_xor_sync(0xFFFFFFFFu, es, o);
    float L = mx + logf(es);
    out[(size_t)row * OUTD + lane] = z0 - L;
    if (lane < 8) out[(size_t)row * OUTD + 32 + lane] = z1 - L;
}

// ---------------- launch (kernel launches ONLY — no CUDA API calls) ------------
extern "C" void kernel_launch(void* const* d_in, const int* in_sizes, int n_in,
                              void* d_out, int out_size) {
    const float* x   = (const float*)d_in[0];
    const int*   ei  = (const int*)d_in[1];      // int32 edge_index (JAX default)
    const float* W1  = (const float*)d_in[2];
    const float* b1  = (const float*)d_in[3];
    const float* g1  = (const float*)d_in[4];
    const float* be1 = (const float*)d_in[5];
    const float* W2  = (const float*)d_in[6];
    const float* b2  = (const float*)d_in[7];
    const float* g2  = (const float*)d_in[8];
    const float* be2 = (const float*)d_in[9];
    const float* W3  = (const float*)d_in[10];
    const float* b3  = (const float*)d_in[11];
    const float* Wl  = (const float*)d_in[12];
    const float* bl  = (const float*)d_in[13];
    float* out = (float*)d_out;

    int n = in_sizes[0] / INF;     // 50000
    int e = in_sizes[1] / 2;       // 800000

    k_init<<<(n + 255) / 256, 256>>>(n);
    k_deg<<<(e + 255) / 256, 256>>>(ei, e, n);
    k_scan<<<1, 1024>>>(n);
    k_scatter<<<(e + 255) / 256, 256>>>(ei, e, n);

    // layer 1: aggregate-first (width 128), then GEMM
    k_aggX<<<n, INF>>>(x);
    dim3 gg((n + BM - 1) / BM, 2);
    k_gemm256<1><<<gg, 256>>>(W1, b1, n);
    k_stats<<<SB, 256>>>(n);
    k_bnparams<<<1, 256>>>(g1, be1, n);

    // layer 2: aggregate f1(m1) (width 256), then GEMM
    k_agg256<<<n, HID>>>();
    k_gemm256<2><<<gg, 256>>>(W2, b2, n);
    k_stats<<<SB, 256>>>(n);
    k_bnparams<<<1, 256>>>(g2, be2, n);

    // layer 3: GEMM-first (f2 fused into A-load, dinv in epilogue), aggregate width 40
    k_gemm40<<<(n + 63) / 64, 256>>>(W3, n);
    k_agg40<<<n, 64>>>(b3);

    // final linear + log_softmax
    k_final<<<(n + 7) / 8, 256>>>(Wl, bl, out, n);
}

// round 7
// speedup vs baseline: 1.0415x; 1.0415x over previous
#include <cuda_runtime.h>
#include <math.h>
#include <stdint.h>

#define NN 50000
#define EE 800000
#define INF 128
#define HID 256
#define OUTD 40
#define SB 512   // stats blocks

// ---------------- scratch (static device globals; no allocation) -------------
__device__ int    g_deg[NN];
__device__ float  g_dinv[NN];
__device__ int    g_rowptr[NN + 1];
__device__ int    g_cursor[NN];
__device__ int    g_col[EE];
__device__ __align__(16) float g_aggx[(size_t)NN * INF];  // Â x
__device__ __align__(16) float g_m[(size_t)NN * HID];     // conv outputs m1 / m2
__device__ __align__(16) float g_agg[(size_t)NN * HID];   // Â f1(m1)
__device__ __align__(16) float g_p3[(size_t)NN * OUTD];   // dinv * (f2(m2) @ W3)
__device__ __align__(16) float g_h3[(size_t)NN * OUTD];   // conv3 output
__device__ float  g_ps[SB * HID];     // per-block partial sums
__device__ float  g_ps2[SB * HID];    // per-block partial sums of squares
__device__ float  g_scale[HID];
__device__ float  g_shift[HID];

// ---------------- graph preprocessing ----------------------------------------
__global__ void k_init(int n) {
    int i = blockIdx.x * blockDim.x + threadIdx.x;
    if (i < n) g_deg[i] = 1;             // self loop
}

// edge_index is int32 (JAX default x64-disabled): row0 = src, row1 = dst
__global__ void k_deg(const int* __restrict__ ei, int e, int n) {
    int i = blockIdx.x * blockDim.x + threadIdx.x;
    if (i < e) {
        int s = ei[i], d = ei[e + i];
        if ((unsigned)s < (unsigned)n && (unsigned)d < (unsigned)n)
            atomicAdd(&g_deg[d], 1);
    }
}

// single-block scan: dinv, rowptr (exclusive over in-degree), cursor
__global__ void k_scan(int n) {
    __shared__ int warpsums[32];
    __shared__ int s_carry;
    int tid = threadIdx.x;  // 1024
    if (tid == 0) { s_carry = 0; g_rowptr[0] = 0; }
    __syncthreads();
    for (int base = 0; base < n; base += 1024) {
        int i = base + tid;
        int v = 0;
        if (i < n) {
            int d = g_deg[i];
            v = d - 1;
            g_dinv[i] = rsqrtf((float)d);
        }
        int x = v;
        #pragma unroll
        for (int o = 1; o < 32; o <<= 1) {
            int y = __shfl_up_sync(0xFFFFFFFFu, x, o);
            if ((tid & 31) >= o) x += y;
        }
        if ((tid & 31) == 31) warpsums[tid >> 5] = x;
        __syncthreads();
        if (tid < 32) {
            int w = warpsums[tid];
            #pragma unroll
            for (int o = 1; o < 32; o <<= 1) {
                int y = __shfl_up_sync(0xFFFFFFFFu, w, o);
                if (tid >= o) w += y;
            }
            warpsums[tid] = w;
        }
        __syncthreads();
        int incl = x + ((tid >= 32) ? warpsums[(tid >> 5) - 1] : 0) + s_carry;
        if (i < n) { g_rowptr[i + 1] = incl; g_cursor[i] = incl - v; }
        __syncthreads();
        if (tid == 1023) s_carry = incl;
        __syncthreads();
    }
}

__global__ void k_scatter(const int* __restrict__ ei, int e, int n) {
    int i = blockIdx.x * blockDim.x + threadIdx.x;
    if (i < e) {
        int s = ei[i], d = ei[e + i];
        if ((unsigned)s < (unsigned)n && (unsigned)d < (unsigned)n) {
            int pos = atomicAdd(&g_cursor[d], 1);
            if ((unsigned)pos < (unsigned)EE) g_col[pos] = s;
        }
    }
}

// ---------------- aggregation kernels ----------------------------------------
// g_aggx[i] = dinv[i] * ( dinv[i]*x[i] + sum_{s in N(i)} dinv[s]*x[s] )
__global__ void k_aggX(const float* __restrict__ x) {
    int i = blockIdx.x, t = threadIdx.x;  // 128 threads
    float di = g_dinv[i];
    float acc = di * x[(size_t)i * INF + t];
    int e0 = g_rowptr[i], e1 = g_rowptr[i + 1];
    int e = e0;
    for (; e + 1 < e1; e += 2) {
        int s0 = g_col[e], s1 = g_col[e + 1];
        float d0 = g_dinv[s0], d1 = g_dinv[s1];
        float v0 = x[(size_t)s0 * INF + t];
        float v1 = x[(size_t)s1 * INF + t];
        acc += d0 * v0 + d1 * v1;
    }
    if (e < e1) {
        int s = g_col[e];
        acc += g_dinv[s] * x[(size_t)s * INF + t];
    }
    g_aggx[(size_t)i * INF + t] = acc * di;
}

// g_agg[i] = dinv[i] * ( dinv[i]*f(m[i]) + sum dinv[s]*f(m[s]) ), f = relu(affine)
__global__ void k_agg256() {
    int i = blockIdx.x, t = threadIdx.x;  // 256 threads
    const float* __restrict__ m = g_m;
    float sc = g_scale[t], sh = g_shift[t];
    float di = g_dinv[i];
    float acc = di * fmaxf(fmaf(m[(size_t)i * HID + t], sc, sh), 0.f);
    int e0 = g_rowptr[i], e1 = g_rowptr[i + 1];
    int e = e0;
    for (; e + 1 < e1; e += 2) {
        int s0 = g_col[e], s1 = g_col[e + 1];
        float d0 = g_dinv[s0], d1 = g_dinv[s1];
        float v0 = fmaxf(fmaf(m[(size_t)s0 * HID + t], sc, sh), 0.f);
        float v1 = fmaxf(fmaf(m[(size_t)s1 * HID + t], sc, sh), 0.f);
        acc += d0 * v0 + d1 * v1;
    }
    if (e < e1) {
        int s = g_col[e];
        acc += g_dinv[s] * fmaxf(fmaf(m[(size_t)s * HID + t], sc, sh), 0.f);
    }
    g_agg[(size_t)i * HID + t] = acc * di;
}

// g_h3[i] = dinv[i]*(p3[i] + sum p3[s]) + b3   (p3 already has dinv[src] folded)
__global__ void k_agg40(const float* __restrict__ b3) {
    int i = blockIdx.x, t = threadIdx.x;  // 64 threads, 40 active
    if (t >= OUTD) return;
    float acc = g_p3[(size_t)i * OUTD + t];
    int e0 = g_rowptr[i], e1 = g_rowptr[i + 1];
    for (int e = e0; e < e1; e++)
        acc += g_p3[(size_t)g_col[e] * OUTD + t];
    g_h3[(size_t)i * OUTD + t] = acc * g_dinv[i] + b3[t];
}

// ---------------- tensor-core 3xTF32 GEMM: g_m[M,256] = A[M,K] @ B[K,256] + b --
// LAYER 1: A = g_aggx (K=128).  LAYER 2: A = g_agg (K=256).
// Block tile 128x128x16, 8 warps (2x4), warp tile 64x32, mma.m16n8k8.tf32.
__device__ __forceinline__ uint32_t f2tf32(float x) {
    uint32_t r;
    asm("cvt.rna.tf32.f32 %0, %1;" : "=r"(r) : "f"(x));
    return r;
}

__device__ __forceinline__ void mma_tf32(float c[4], const uint32_t a[4], const uint32_t b[2]) {
    asm volatile(
        "mma.sync.aligned.m16n8k8.row.col.f32.tf32.tf32.f32 "
        "{%0,%1,%2,%3}, {%4,%5,%6,%7}, {%8,%9}, {%0,%1,%2,%3};"
        : "+f"(c[0]), "+f"(c[1]), "+f"(c[2]), "+f"(c[3])
        : "r"(a[0]), "r"(a[1]), "r"(a[2]), "r"(a[3]), "r"(b[0]), "r"(b[1]));
}

#define TPAD 136  // stride: 136 % 32 == 8 -> conflict-free fragment loads

template <int LAYER>
__global__ __launch_bounds__(256) void k_gemm256_tc(
    const float* __restrict__ B, const float* __restrict__ bias, int M) {
    constexpr int K = (LAYER == 1) ? INF : HID;
    const float* __restrict__ A = (LAYER == 1) ? g_aggx : g_agg;
    float* __restrict__ C = g_m;

    __shared__ uint32_t Ah[16][TPAD], Al[16][TPAD];
    __shared__ uint32_t Bh[16][TPAD], Bl[16][TPAD];

    int t = threadIdx.x;
    int warp = t >> 5, lane = t & 31;
    int lr = lane >> 2, lc = lane & 3;
    int warpM = (warp >> 2) * 64;
    int warpN = (warp & 3) * 32;
    int rowBase = blockIdx.x * 128;
    int colBase = blockIdx.y * 128;

    float acc[4][4][4];
    #pragma unroll
    for (int mt = 0; mt < 4; mt++)
        #pragma unroll
        for (int nt = 0; nt < 4; nt++)
            #pragma unroll
            for (int j = 0; j < 4; j++) acc[mt][nt][j] = 0.f;

    for (int kk = 0; kk < K; kk += 16) {
        // -- A fill: 128 rows x 16 k = 512 float4 slots, transpose into Ah/Al[k][m]
        for (int s = t; s < 512; s += 256) {
            int row = s >> 2;
            int k4  = (s & 3) << 2;
            int r = rowBase + row;
            float4 v = make_float4(0.f, 0.f, 0.f, 0.f);
            if (r < M) v = *(const float4*)(A + (size_t)r * K + kk + k4);
            float f[4] = {v.x, v.y, v.z, v.w};
            #pragma unroll
            for (int j = 0; j < 4; j++) {
                uint32_t hi = f2tf32(f[j]);
                float lof = f[j] - __uint_as_float(hi);
                Ah[k4 + j][row] = hi;
                Al[k4 + j][row] = f2tf32(lof);
            }
        }
        // -- B fill: 16 k-rows x 128 cols = 512 float4 slots, vectorized stores
        for (int s = t; s < 512; s += 256) {
            int kr = s >> 5;
            int n4 = (s & 31) << 2;
            float4 v = *(const float4*)(B + (size_t)(kk + kr) * 256 + colBase + n4);
            float f[4] = {v.x, v.y, v.z, v.w};
            uint4 hb, lb;
            uint32_t* hp = (uint32_t*)&hb;
            uint32_t* lp = (uint32_t*)&lb;
            #pragma unroll
            for (int j = 0; j < 4; j++) {
                uint32_t hi = f2tf32(f[j]);
                hp[j] = hi;
                lp[j] = f2tf32(f[j] - __uint_as_float(hi));
            }
            *(uint4*)&Bh[kr][n4] = hb;
            *(uint4*)&Bl[kr][n4] = lb;
        }
        __syncthreads();

        #pragma unroll
        for (int s = 0; s < 2; s++) {
            int kc = s * 8;
            uint32_t ah[4][4], al[4][4], bh[4][2], bl[4][2];
            #pragma unroll
            for (int nt = 0; nt < 4; nt++) {
                int nc = warpN + nt * 8 + lr;
                bh[nt][0] = Bh[kc + lc][nc];
                bh[nt][1] = Bh[kc + 4 + lc][nc];
                bl[nt][0] = Bl[kc + lc][nc];
                bl[nt][1] = Bl[kc + 4 + lc][nc];
            }
            #pragma unroll
            for (int mt = 0; mt < 4; mt++) {
                int m = warpM + mt * 16 + lr;
                ah[mt][0] = Ah[kc + lc][m];
                ah[mt][1] = Ah[kc + lc][m + 8];
                ah[mt][2] = Ah[kc + 4 + lc][m];
                ah[mt][3] = Ah[kc + 4 + lc][m + 8];
                al[mt][0] = Al[kc + lc][m];
                al[mt][1] = Al[kc + lc][m + 8];
                al[mt][2] = Al[kc + 4 + lc][m];
                al[mt][3] = Al[kc + 4 + lc][m + 8];
            }
            #pragma unroll
            for (int mt = 0; mt < 4; mt++)
                #pragma unroll
                for (int nt = 0; nt < 4; nt++) {
                    mma_tf32(acc[mt][nt], ah[mt], bh[nt]);   // hi*hi
                    mma_tf32(acc[mt][nt], ah[mt], bl[nt]);   // hi*lo
                    mma_tf32(acc[mt][nt], al[mt], bh[nt]);   // lo*hi
                }
        }
        __syncthreads();
    }

    // epilogue: bias add + store (c0,c1 contiguous cols; c2,c3 at row+8)
    #pragma unroll
    for (int nt = 0; nt < 4; nt++) {
        int col = colBase + warpN + nt * 8 + 2 * lc;
        float b0 = bias[col], b1 = bias[col + 1];
        #pragma unroll
        for (int mt = 0; mt < 4; mt++) {
            int r0 = rowBase + warpM + mt * 16 + lr;
            if (r0 < M) {
                float2 o = make_float2(acc[mt][nt][0] + b0, acc[mt][nt][1] + b1);
                *(float2*)(C + (size_t)r0 * 256 + col) = o;
            }
            int r1 = r0 + 8;
            if (r1 < M) {
                float2 o = make_float2(acc[mt][nt][2] + b0, acc[mt][nt][3] + b1);
                *(float2*)(C + (size_t)r1 * 256 + col) = o;
            }
        }
    }
}

// ---------------- GEMM: g_p3[M,40] = dinv * ( f2(g_m)[M,256] @ W3[256,40] ) ---
__global__ __launch_bounds__(256) void k_gemm40(
    const float* __restrict__ W, int M) {
    const float* __restrict__ A = g_m;
    __shared__ float As[32][65];
    __shared__ float Ws[32][40];
    __shared__ float ssc[HID], ssh[HID];
    int tid = threadIdx.x;
    ssc[tid] = g_scale[tid];
    ssh[tid] = g_shift[tid];
    __syncthreads();

    int rowBase = blockIdx.x * 64;
    int r = tid & 63;
    int cg = tid >> 6;  // 0..3 -> cols cg*10..cg*10+9
    float acc[10];
    #pragma unroll
    for (int j = 0; j < 10; j++) acc[j] = 0.f;

    int aRow = tid >> 3;        // 0..31
    int aCol = (tid & 7) << 2;  // 0..28

    for (int kk = 0; kk < HID; kk += 32) {
        #pragma unroll
        for (int rr = 0; rr < 2; rr++) {
            int row = rowBase + aRow + rr * 32;
            float4 v = make_float4(0.f, 0.f, 0.f, 0.f);
            if (row < M) v = *(const float4*)(A + (size_t)row * HID + kk + aCol);
            int c = kk + aCol;
            As[aCol + 0][aRow + rr * 32] = fmaxf(fmaf(v.x, ssc[c + 0], ssh[c + 0]), 0.f);
            As[aCol + 1][aRow + rr * 32] = fmaxf(fmaf(v.y, ssc[c + 1], ssh[c + 1]), 0.f);
            As[aCol + 2][aRow + rr * 32] = fmaxf(fmaf(v.z, ssc[c + 2], ssh[c + 2]), 0.f);
            As[aCol + 3][aRow + rr * 32] = fmaxf(fmaf(v.w, ssc[c + 3], ssh[c + 3]), 0.f);
        }
        for (int idx = tid; idx < 32 * OUTD; idx += 256) {
            int kr = idx / OUTD, c = idx % OUTD;
            Ws[kr][c] = W[(size_t)(kk + kr) * OUTD + c];
        }
        __syncthreads();
        #pragma unroll
        for (int k = 0; k < 32; k++) {
            float a = As[k][r];
            #pragma unroll
            for (int j = 0; j < 10; j++)
                acc[j] = fmaf(a, Ws[k][cg * 10 + j], acc[j]);
        }
        __syncthreads();
    }
    int row = rowBase + r;
    if (row < M) {
        float d = g_dinv[row];
        #pragma unroll
        for (int j = 0; j < 10; j++)
            g_p3[(size_t)row * OUTD + cg * 10 + j] = acc[j] * d;
    }
}

// ---------------- BN stats (fp32 block partials, no atomics) -------------------
__global__ void k_stats(int n) {
    int t = threadIdx.x;  // 256
    int b = blockIdx.x;   // SB blocks
    const float* __restrict__ m = g_m;
    float s = 0.f, s2 = 0.f;
    for (int r = b; r < n; r += SB) {
        float v = m[(size_t)r * HID + t];
        s += v;
        s2 = fmaf(v, v, s2);
    }
    g_ps[b * HID + t]  = s;
    g_ps2[b * HID + t] = s2;
}

__global__ void k_bnparams(const float* __restrict__ g, const float* __restrict__ be, int n) {
    int t = threadIdx.x;  // 256
    float s = 0.f, s2 = 0.f;
    #pragma unroll 8
    for (int b = 0; b < SB; b++) {
        s  += g_ps[b * HID + t];
        s2 += g_ps2[b * HID + t];
    }
    float inv_n = 1.f / (float)n;
    float mean = s * inv_n;
    float var  = fmaf(s2, inv_n, -mean * mean);
    float rs = rsqrtf(var + 1e-5f);
    float sc = rs * g[t];
    g_scale[t] = sc;
    g_shift[t] = be[t] - mean * sc;
}

// ---------------- final: out = log_softmax(g_h3 @ Wl + bl) ---------------------
__global__ void k_final(const float* __restrict__ Wl, const float* __restrict__ bl,
                        float* __restrict__ out, int n) {
    __shared__ float sW[OUTD * OUTD];
    __shared__ float sb[OUTD];
    int tid = threadIdx.x;  // 256
    for (int i = tid; i < OUTD * OUTD; i += 256) sW[i] = Wl[i];
    if (tid < OUTD) sb[tid] = bl[tid];
    __syncthreads();
    int warp = tid >> 5, lane = tid & 31;
    int row = blockIdx.x * 8 + warp;
    if (row >= n) return;
    const float* a = g_h3 + (size_t)row * OUTD;
    float a_lo = a[lane];
    float a_hi = (lane < 8) ? a[32 + lane] : 0.f;
    float z0 = sb[lane];
    float z1 = (lane < 8) ? sb[32 + lane] : -1e30f;
    #pragma unroll
    for (int k = 0; k < OUTD; k++) {
        float ak = (k < 32) ? __shfl_sync(0xFFFFFFFFu, a_lo, k)
                            : __shfl_sync(0xFFFFFFFFu, a_hi, k - 32);
        z0 = fmaf(ak, sW[k * OUTD + lane], z0);
        if (lane < 8) z1 = fmaf(ak, sW[k * OUTD + 32 + lane], z1);
    }
    float mx = fmaxf(z0, z1);
    #pragma unroll
    for (int o = 16; o; o >>= 1) mx = fmaxf(mx, __shfl_xor_sync(0xFFFFFFFFu, mx, o));
    float es = expf(z0 - mx) + ((lane < 8) ? expf(z1 - mx) : 0.f);
    #pragma unroll
    for (int o = 16; o; o >>= 1) es += __shfl_xor_sync(0xFFFFFFFFu, es, o);
    float L = mx + logf(es);
    out[(size_t)row * OUTD + lane] = z0 - L;
    if (lane < 8) out[(size_t)row * OUTD + 32 + lane] = z1 - L;
}

// ---------------- launch (kernel launches ONLY — no CUDA API calls) ------------
extern "C" void kernel_launch(void* const* d_in, const int* in_sizes, int n_in,
                              void* d_out, int out_size) {
    const float* x   = (const float*)d_in[0];
    const int*   ei  = (const int*)d_in[1];      // int32 edge_index (JAX default)
    const float* W1  = (const float*)d_in[2];
    const float* b1  = (const float*)d_in[3];
    const float* g1  = (const float*)d_in[4];
    const float* be1 = (const float*)d_in[5];
    const float* W2  = (const float*)d_in[6];
    const float* b2  = (const float*)d_in[7];
    const float* g2  = (const float*)d_in[8];
    const float* be2 = (const float*)d_in[9];
    const float* W3  = (const float*)d_in[10];
    const float* b3  = (const float*)d_in[11];
    const float* Wl  = (const float*)d_in[12];
    const float* bl  = (const float*)d_in[13];
    float* out = (float*)d_out;

    int n = in_sizes[0] / INF;     // 50000
    int e = in_sizes[1] / 2;       // 800000

    k_init<<<(n + 255) / 256, 256>>>(n);
    k_deg<<<(e + 255) / 256, 256>>>(ei, e, n);
    k_scan<<<1, 1024>>>(n);
    k_scatter<<<(e + 255) / 256, 256>>>(ei, e, n);

    // layer 1: aggregate-first (width 128), then TC GEMM
    k_aggX<<<n, INF>>>(x);
    dim3 gg((n + 127) / 128, 2);
    k_gemm256_tc<1><<<gg, 256>>>(W1, b1, n);
    k_stats<<<SB, 256>>>(n);
    k_bnparams<<<1, 256>>>(g1, be1, n);

    // layer 2: aggregate f1(m1) (width 256), then TC GEMM
    k_agg256<<<n, HID>>>();
    k_gemm256_tc<2><<<gg, 256>>>(W2, b2, n);
    k_stats<<<SB, 256>>>(n);
    k_bnparams<<<1, 256>>>(g2, be2, n);

    // layer 3: GEMM-first (f2 fused into A-load, dinv in epilogue), aggregate width 40
    k_gemm40<<<(n + 63) / 64, 256>>>(W3, n);
    k_agg40<<<n, 64>>>(b3);

    // final linear + log_softmax
    k_final<<<(n + 7) / 8, 256>>>(Wl, bl, out, n);
}

// round 9
// speedup vs baseline: 1.2910x; 1.2395x over previous
#include <cuda_runtime.h>
#include <math.h>
#include <stdint.h>

#define NN 50000
#define EE 800000
#define INF 128
#define HID 256
#define OUTD 40

// ---------------- scratch (static device globals; no allocation) -------------
__device__ int    g_deg[NN];
__device__ float  g_dinv[NN];
__device__ int    g_rowptr[NN + 1];
__device__ int    g_cursor[NN];
__device__ int    g_col[EE];
__device__ int    g_bsum[64];
__device__ int    g_boff[64];
__device__ __align__(16) float g_aggx[(size_t)NN * INF];  // Â x
__device__ __align__(16) float g_m[(size_t)NN * HID];     // conv outputs m1 / m2
__device__ __align__(16) float g_agg[(size_t)NN * HID];   // Â f1(m1)
__device__ __align__(16) float g_p3[(size_t)NN * OUTD];   // dinv * (f2(m2) @ W3)
__device__ __align__(16) float g_h3[(size_t)NN * OUTD];   // conv3 output
__device__ float  g_sumf[HID];     // fused BN stats (fp32, atomic)
__device__ float  g_sum2f[HID];
__device__ float  g_scale[HID];
__device__ float  g_shift[HID];

// ---------------- graph preprocessing ----------------------------------------
__global__ void k_init(int n) {
    int i = blockIdx.x * blockDim.x + threadIdx.x;
    if (i < n) g_deg[i] = 1;             // self loop
    if (i < HID) { g_sumf[i] = 0.f; g_sum2f[i] = 0.f; }
}

// edge_index is int32 (JAX default x64-disabled): row0 = src, row1 = dst
__global__ void k_deg(const int* __restrict__ ei, int e, int n) {
    int i = blockIdx.x * blockDim.x + threadIdx.x;
    if (i < e) {
        int s = ei[i], d = ei[e + i];
        if ((unsigned)s < (unsigned)n && (unsigned)d < (unsigned)n)
            atomicAdd(&g_deg[d], 1);
    }
}

// ---- multi-block scan over (deg-1): phase 1 = per-block inclusive scan ------
__global__ __launch_bounds__(1024) void k_scan1(int n) {
    __shared__ int warpsums[32];
    int b = blockIdx.x, tid = threadIdx.x;
    int i = b * 1024 + tid;
    int v = 0;
    if (i < n) {
        int d = g_deg[i];
        v = d - 1;
        g_dinv[i] = rsqrtf((float)d);
    }
    int x = v;
    #pragma unroll
    for (int o = 1; o < 32; o <<= 1) {
        int y = __shfl_up_sync(0xFFFFFFFFu, x, o);
        if ((tid & 31) >= o) x += y;
    }
    if ((tid & 31) == 31) warpsums[tid >> 5] = x;
    __syncthreads();
    if (tid < 32) {
        int w = warpsums[tid];
        #pragma unroll
        for (int o = 1; o < 32; o <<= 1) {
            int y = __shfl_up_sync(0xFFFFFFFFu, w, o);
            if (tid >= o) w += y;
        }
        warpsums[tid] = w;
    }
    __syncthreads();
    int incl = x + ((tid >= 32) ? warpsums[(tid >> 5) - 1] : 0);
    if (i < n) g_rowptr[i + 1] = incl;              // local inclusive
    if (tid == 1023) g_bsum[b] = incl;              // block total
}

// phase 2: exclusive scan over <=64 block totals (one block, 64 threads)
__global__ void k_scan2(int nb) {
    __shared__ int w0;
    int tid = threadIdx.x;  // 64
    int v = (tid < nb) ? g_bsum[tid] : 0;
    int x = v;
    #pragma unroll
    for (int o = 1; o < 32; o <<= 1) {
        int y = __shfl_up_sync(0xFFFFFFFFu, x, o);
        if ((tid & 31) >= o) x += y;
    }
    if (tid == 31) w0 = x;
    __syncthreads();
    int incl = x + ((tid >= 32) ? w0 : 0);
    g_boff[tid] = incl - v;   // exclusive prefix
}

// phase 3: apply offsets, finalize rowptr + cursor
__global__ __launch_bounds__(1024) void k_scan3(int n) {
    int b = blockIdx.x;
    int i = b * 1024 + threadIdx.x;
    if (i < n) {
        int val = g_rowptr[i + 1] + g_boff[b];
        g_rowptr[i + 1] = val;
        g_cursor[i] = val - (g_deg[i] - 1);
        if (i == 0) g_rowptr[0] = 0;
    }
}

__global__ void k_scatter(const int* __restrict__ ei, int e, int n) {
    int i = blockIdx.x * blockDim.x + threadIdx.x;
    if (i < e) {
        int s = ei[i], d = ei[e + i];
        if ((unsigned)s < (unsigned)n && (unsigned)d < (unsigned)n) {
            int pos = atomicAdd(&g_cursor[d], 1);
            if ((unsigned)pos < (unsigned)EE) g_col[pos] = s;
        }
    }
}

// ---------------- aggregation kernels (float4 lanes) ---------------------------
// g_aggx[i] = dinv[i] * ( dinv[i]*x[i] + sum_{s in N(i)} dinv[s]*x[s] )
__global__ void k_aggX(const float* __restrict__ x) {
    int i = blockIdx.x, t = threadIdx.x;  // 32 threads, float4 each (128 floats)
    const float4* __restrict__ x4 = (const float4*)x;
    float di = g_dinv[i];
    float4 v = x4[(size_t)i * 32 + t];
    float4 acc = make_float4(di * v.x, di * v.y, di * v.z, di * v.w);
    int e0 = g_rowptr[i], e1 = g_rowptr[i + 1];
    int e = e0;
    for (; e + 1 < e1; e += 2) {
        int s0 = g_col[e], s1 = g_col[e + 1];
        float d0 = g_dinv[s0], d1 = g_dinv[s1];
        float4 v0 = x4[(size_t)s0 * 32 + t];
        float4 v1 = x4[(size_t)s1 * 32 + t];
        acc.x += d0 * v0.x + d1 * v1.x;
        acc.y += d0 * v0.y + d1 * v1.y;
        acc.z += d0 * v0.z + d1 * v1.z;
        acc.w += d0 * v0.w + d1 * v1.w;
    }
    if (e < e1) {
        int s = g_col[e];
        float d = g_dinv[s];
        float4 v0 = x4[(size_t)s * 32 + t];
        acc.x += d * v0.x; acc.y += d * v0.y; acc.z += d * v0.z; acc.w += d * v0.w;
    }
    ((float4*)g_aggx)[(size_t)i * 32 + t] =
        make_float4(acc.x * di, acc.y * di, acc.z * di, acc.w * di);
}

__device__ __forceinline__ float4 bnrelu4(float4 v, float4 sc, float4 sh) {
    return make_float4(fmaxf(fmaf(v.x, sc.x, sh.x), 0.f),
                       fmaxf(fmaf(v.y, sc.y, sh.y), 0.f),
                       fmaxf(fmaf(v.z, sc.z, sh.z), 0.f),
                       fmaxf(fmaf(v.w, sc.w, sh.w), 0.f));
}

// g_agg[i] = dinv[i] * ( dinv[i]*f(m[i]) + sum dinv[s]*f(m[s]) ), f = relu(affine)
__global__ void k_agg256() {
    int i = blockIdx.x, t = threadIdx.x;  // 64 threads, float4 each (256 floats)
    const float4* __restrict__ m4 = (const float4*)g_m;
    float4 sc = ((const float4*)g_scale)[t];
    float4 sh = ((const float4*)g_shift)[t];
    float di = g_dinv[i];
    float4 f = bnrelu4(m4[(size_t)i * 64 + t], sc, sh);
    float4 acc = make_float4(di * f.x, di * f.y, di * f.z, di * f.w);
    int e0 = g_rowptr[i], e1 = g_rowptr[i + 1];
    int e = e0;
    for (; e + 1 < e1; e += 2) {
        int s0 = g_col[e], s1 = g_col[e + 1];
        float d0 = g_dinv[s0], d1 = g_dinv[s1];
        float4 f0 = bnrelu4(m4[(size_t)s0 * 64 + t], sc, sh);
        float4 f1 = bnrelu4(m4[(size_t)s1 * 64 + t], sc, sh);
        acc.x += d0 * f0.x + d1 * f1.x;
        acc.y += d0 * f0.y + d1 * f1.y;
        acc.z += d0 * f0.z + d1 * f1.z;
        acc.w += d0 * f0.w + d1 * f1.w;
    }
    if (e < e1) {
        int s = g_col[e];
        float d = g_dinv[s];
        float4 f0 = bnrelu4(m4[(size_t)s * 64 + t], sc, sh);
        acc.x += d * f0.x; acc.y += d * f0.y; acc.z += d * f0.z; acc.w += d * f0.w;
    }
    ((float4*)g_agg)[(size_t)i * 64 + t] =
        make_float4(acc.x * di, acc.y * di, acc.z * di, acc.w * di);
}

// g_h3[i] = dinv[i]*(p3[i] + sum p3[s]) + b3   (p3 already has dinv[src] folded)
// warp per node, lanes 0..9 hold float4 (40 floats)
__global__ void k_agg40(const float* __restrict__ b3, int n) {
    int node = blockIdx.x * 8 + (threadIdx.x >> 5);
    int lane = threadIdx.x & 31;
    if (node >= n || lane >= 10) return;
    const float4* __restrict__ p4 = (const float4*)g_p3;
    float4 acc = p4[(size_t)node * 10 + lane];
    int e0 = g_rowptr[node], e1 = g_rowptr[node + 1];
    int e = e0;
    for (; e + 1 < e1; e += 2) {
        int s0 = g_col[e], s1 = g_col[e + 1];
        float4 v0 = p4[(size_t)s0 * 10 + lane];
        float4 v1 = p4[(size_t)s1 * 10 + lane];
        acc.x += v0.x + v1.x; acc.y += v0.y + v1.y;
        acc.z += v0.z + v1.z; acc.w += v0.w + v1.w;
    }
    if (e < e1) {
        float4 v0 = p4[(size_t)g_col[e] * 10 + lane];
        acc.x += v0.x; acc.y += v0.y; acc.z += v0.z; acc.w += v0.w;
    }
    float di = g_dinv[node];
    float4 bv = ((const float4*)b3)[lane];
    ((float4*)g_h3)[(size_t)node * 10 + lane] =
        make_float4(acc.x * di + bv.x, acc.y * di + bv.y,
                    acc.z * di + bv.z, acc.w * di + bv.w);
}

// ---------------- tensor-core 3xTF32 GEMM + fused BN stats ---------------------
__device__ __forceinline__ uint32_t f2tf32(float x) {
    uint32_t r;
    asm("cvt.rna.tf32.f32 %0, %1;" : "=r"(r) : "f"(x));
    return r;
}

__device__ __forceinline__ void mma_tf32(float c[4], const uint32_t a[4], const uint32_t b[2]) {
    asm volatile(
        "mma.sync.aligned.m16n8k8.row.col.f32.tf32.tf32.f32 "
        "{%0,%1,%2,%3}, {%4,%5,%6,%7}, {%8,%9}, {%0,%1,%2,%3};"
        : "+f"(c[0]), "+f"(c[1]), "+f"(c[2]), "+f"(c[3])
        : "r"(a[0]), "r"(a[1]), "r"(a[2]), "r"(a[3]), "r"(b[0]), "r"(b[1]));
}

#define TPAD 136  // stride: 136 % 32 == 8 -> conflict-free fragment loads

template <int LAYER>
__global__ __launch_bounds__(256) void k_gemm256_tc(
    const float* __restrict__ B, const float* __restrict__ bias, int M) {
    constexpr int K = (LAYER == 1) ? INF : HID;
    const float* __restrict__ A = (LAYER == 1) ? g_aggx : g_agg;
    float* __restrict__ C = g_m;

    __shared__ uint32_t Ah[16][TPAD], Al[16][TPAD];
    __shared__ uint32_t Bh[16][TPAD], Bl[16][TPAD];
    __shared__ float s_s[128], s_s2[128];

    int t = threadIdx.x;
    int warp = t >> 5, lane = t & 31;
    int lr = lane >> 2, lc = lane & 3;
    int warpM = (warp >> 2) * 64;
    int warpN = (warp & 3) * 32;
    int rowBase = blockIdx.x * 128;
    int colBase = blockIdx.y * 128;

    if (t < 128) { s_s[t] = 0.f; s_s2[t] = 0.f; }

    float acc[4][4][4];
    #pragma unroll
    for (int mt = 0; mt < 4; mt++)
        #pragma unroll
        for (int nt = 0; nt < 4; nt++)
            #pragma unroll
            for (int j = 0; j < 4; j++) acc[mt][nt][j] = 0.f;

    for (int kk = 0; kk < K; kk += 16) {
        // -- A fill: 128 rows x 16 k = 512 float4 slots, transpose into Ah/Al[k][m]
        for (int s = t; s < 512; s += 256) {
            int row = s >> 2;
            int k4  = (s & 3) << 2;
            int r = rowBase + row;
            float4 v = make_float4(0.f, 0.f, 0.f, 0.f);
            if (r < M) v = *(const float4*)(A + (size_t)r * K + kk + k4);
            float f[4] = {v.x, v.y, v.z, v.w};
            #pragma unroll
            for (int j = 0; j < 4; j++) {
                uint32_t hi = f2tf32(f[j]);
                float lof = f[j] - __uint_as_float(hi);
                Ah[k4 + j][row] = hi;
                Al[k4 + j][row] = f2tf32(lof);
            }
        }
        // -- B fill: 16 k-rows x 128 cols = 512 float4 slots, vectorized stores
        for (int s = t; s < 512; s += 256) {
            int kr = s >> 5;
            int n4 = (s & 31) << 2;
            float4 v = *(const float4*)(B + (size_t)(kk + kr) * 256 + colBase + n4);
            float f[4] = {v.x, v.y, v.z, v.w};
            uint4 hb, lb;
            uint32_t* hp = (uint32_t*)&hb;
            uint32_t* lp = (uint32_t*)&lb;
            #pragma unroll
            for (int j = 0; j < 4; j++) {
                uint32_t hi = f2tf32(f[j]);
                hp[j] = hi;
                lp[j] = f2tf32(f[j] - __uint_as_float(hi));
            }
            *(uint4*)&Bh[kr][n4] = hb;
            *(uint4*)&Bl[kr][n4] = lb;
        }
        __syncthreads();

        #pragma unroll
        for (int s = 0; s < 2; s++) {
            int kc = s * 8;
            uint32_t ah[4][4], al[4][4], bh[4][2], bl[4][2];
            #pragma unroll
            for (int nt = 0; nt < 4; nt++) {
                int nc = warpN + nt * 8 + lr;
                bh[nt][0] = Bh[kc + lc][nc];
                bh[nt][1] = Bh[kc + 4 + lc][nc];
                bl[nt][0] = Bl[kc + lc][nc];
                bl[nt][1] = Bl[kc + 4 + lc][nc];
            }
            #pragma unroll
            for (int mt = 0; mt < 4; mt++) {
                int m = warpM + mt * 16 + lr;
                ah[mt][0] = Ah[kc + lc][m];
                ah[mt][1] = Ah[kc + lc][m + 8];
                ah[mt][2] = Ah[kc + 4 + lc][m];
                ah[mt][3] = Ah[kc + 4 + lc][m + 8];
                al[mt][0] = Al[kc + lc][m];
                al[mt][1] = Al[kc + lc][m + 8];
                al[mt][2] = Al[kc + 4 + lc][m];
                al[mt][3] = Al[kc + 4 + lc][m + 8];
            }
            #pragma unroll
            for (int mt = 0; mt < 4; mt++)
                #pragma unroll
                for (int nt = 0; nt < 4; nt++) {
                    mma_tf32(acc[mt][nt], ah[mt], bh[nt]);   // hi*hi
                    mma_tf32(acc[mt][nt], ah[mt], bl[nt]);   // hi*lo
                    mma_tf32(acc[mt][nt], al[mt], bh[nt]);   // lo*hi
                }
        }
        __syncthreads();
    }

    // epilogue: bias add + store + fused BN-stat accumulation
    float ls[8], ls2[8];
    #pragma unroll
    for (int j = 0; j < 8; j++) { ls[j] = 0.f; ls2[j] = 0.f; }

    #pragma unroll
    for (int nt = 0; nt < 4; nt++) {
        int col = colBase + warpN + nt * 8 + 2 * lc;
        float b0 = bias[col], b1 = bias[col + 1];
        #pragma unroll
        for (int mt = 0; mt < 4; mt++) {
            int r0 = rowBase + warpM + mt * 16 + lr;
            if (r0 < M) {
                float o0 = acc[mt][nt][0] + b0, o1 = acc[mt][nt][1] + b1;
                *(float2*)(C + (size_t)r0 * 256 + col) = make_float2(o0, o1);
                ls[nt * 2]      += o0;  ls2[nt * 2]      = fmaf(o0, o0, ls2[nt * 2]);
                ls[nt * 2 + 1]  += o1;  ls2[nt * 2 + 1]  = fmaf(o1, o1, ls2[nt * 2 + 1]);
            }
            int r1 = r0 + 8;
            if (r1 < M) {
                float o2 = acc[mt][nt][2] + b0, o3 = acc[mt][nt][3] + b1;
                *(float2*)(C + (size_t)r1 * 256 + col) = make_float2(o2, o3);
                ls[nt * 2]      += o2;  ls2[nt * 2]      = fmaf(o2, o2, ls2[nt * 2]);
                ls[nt * 2 + 1]  += o3;  ls2[nt * 2 + 1]  = fmaf(o3, o3, ls2[nt * 2 + 1]);
            }
        }
    }
    __syncthreads();   // s_s zero-init visible
    #pragma unroll
    for (int nt = 0; nt < 4; nt++) {
        int c0 = warpN + nt * 8 + 2 * lc;   // block-local column
        atomicAdd(&s_s[c0],      ls[nt * 2]);
        atomicAdd(&s_s2[c0],     ls2[nt * 2]);
        atomicAdd(&s_s[c0 + 1],  ls[nt * 2 + 1]);
        atomicAdd(&s_s2[c0 + 1], ls2[nt * 2 + 1]);
    }
    __syncthreads();
    if (t < 128) {
        atomicAdd(&g_sumf[colBase + t],  s_s[t]);
        atomicAdd(&g_sum2f[colBase + t], s_s2[t]);
    }
}

// ---------------- GEMM: g_p3[M,40] = dinv * ( f2(g_m)[M,256] @ W3[256,40] ) ---
__global__ __launch_bounds__(256) void k_gemm40(
    const float* __restrict__ W, int M) {
    const float* __restrict__ A = g_m;
    __shared__ float As[32][65];
    __shared__ float Ws[32][40];
    __shared__ float ssc[HID], ssh[HID];
    int tid = threadIdx.x;
    ssc[tid] = g_scale[tid];
    ssh[tid] = g_shift[tid];
    __syncthreads();

    int rowBase = blockIdx.x * 64;
    int r = tid & 63;
    int cg = tid >> 6;  // 0..3 -> cols cg*10..cg*10+9
    float acc[10];
    #pragma unroll
    for (int j = 0; j < 10; j++) acc[j] = 0.f;

    int aRow = tid >> 3;        // 0..31
    int aCol = (tid & 7) << 2;  // 0..28

    for (int kk = 0; kk < HID; kk += 32) {
        #pragma unroll
        for (int rr = 0; rr < 2; rr++) {
            int row = rowBase + aRow + rr * 32;
            float4 v = make_float4(0.f, 0.f, 0.f, 0.f);
            if (row < M) v = *(const float4*)(A + (size_t)row * HID + kk + aCol);
            int c = kk + aCol;
            As[aCol + 0][aRow + rr * 32] = fmaxf(fmaf(v.x, ssc[c + 0], ssh[c + 0]), 0.f);
            As[aCol + 1][aRow + rr * 32] = fmaxf(fmaf(v.y, ssc[c + 1], ssh[c + 1]), 0.f);
            As[aCol + 2][aRow + rr * 32] = fmaxf(fmaf(v.z, ssc[c + 2], ssh[c + 2]), 0.f);
            As[aCol + 3][aRow + rr * 32] = fmaxf(fmaf(v.w, ssc[c + 3], ssh[c + 3]), 0.f);
        }
        for (int idx = tid; idx < 32 * OUTD; idx += 256) {
            int kr = idx / OUTD, c = idx % OUTD;
            Ws[kr][c] = W[(size_t)(kk + kr) * OUTD + c];
        }
        __syncthreads();
        #pragma unroll
        for (int k = 0; k < 32; k++) {
            float a = As[k][r];
            #pragma unroll
            for (int j = 0; j < 10; j++)
                acc[j] = fmaf(a, Ws[k][cg * 10 + j], acc[j]);
        }
        __syncthreads();
    }
    int row = rowBase + r;
    if (row < M) {
        float d = g_dinv[row];
        #pragma unroll
        for (int j = 0; j < 10; j++)
            g_p3[(size_t)row * OUTD + cg * 10 + j] = acc[j] * d;
    }
}

// ---------------- BN params from fused stats -----------------------------------
__global__ void k_bnparams(const float* __restrict__ g, const float* __restrict__ be, int n) {
    int t = threadIdx.x;  // 256
    float s = g_sumf[t], s2 = g_sum2f[t];
    g_sumf[t] = 0.f;
    g_sum2f[t] = 0.f;
    float inv_n = 1.f / (float)n;
    float mean = s * inv_n;
    float var  = fmaf(s2, inv_n, -mean * mean);
    float rs = rsqrtf(var + 1e-5f);
    float sc = rs * g[t];
    g_scale[t] = sc;
    g_shift[t] = be[t] - mean * sc;
}

// ---------------- final: out = log_softmax(g_h3 @ Wl + bl) ---------------------
__global__ void k_final(const float* __restrict__ Wl, const float* __restrict__ bl,
                        float* __restrict__ out, int n) {
    __shared__ float sW[OUTD * OUTD];
    __shared__ float sb[OUTD];
    int tid = threadIdx.x;  // 256
    for (int i = tid; i < OUTD * OUTD; i += 256) sW[i] = Wl[i];
    if (tid < OUTD) sb[tid] = bl[tid];
    __syncthreads();
    int warp = tid >> 5, lane = tid & 31;
    int row = blockIdx.x * 8 + warp;
    if (row >= n) return;
    const float* a = g_h3 + (size_t)row * OUTD;
    float a_lo = a[lane];
    float a_hi = (lane < 8) ? a[32 + lane] : 0.f;
    float z0 = sb[lane];
    float z1 = (lane < 8) ? sb[32 + lane] : -1e30f;
    #pragma unroll
    for (int k = 0; k < OUTD; k++) {
        float ak = (k < 32) ? __shfl_sync(0xFFFFFFFFu, a_lo, k)
                            : __shfl_sync(0xFFFFFFFFu, a_hi, k - 32);
        z0 = fmaf(ak, sW[k * OUTD + lane], z0);
        if (lane < 8) z1 = fmaf(ak, sW[k * OUTD + 32 + lane], z1);
    }
    float mx = fmaxf(z0, z1);
    #pragma unroll
    for (int o = 16; o; o >>= 1) mx = fmaxf(mx, __shfl_xor_sync(0xFFFFFFFFu, mx, o));
    float es = expf(z0 - mx) + ((lane < 8) ? expf(z1 - mx) : 0.f);
    #pragma unroll
    for (int o = 16; o; o >>= 1) es += __shfl_xor_sync(0xFFFFFFFFu, es, o);
    float L = mx + logf(es);
    out[(size_t)row * OUTD + lane] = z0 - L;
    if (lane < 8) out[(size_t)row * OUTD + 32 + lane] = z1 - L;
}

// ---------------- launch (kernel launches ONLY — no CUDA API calls) ------------
extern "C" void kernel_launch(void* const* d_in, const int* in_sizes, int n_in,
                              void* d_out, int out_size) {
    const float* x   = (const float*)d_in[0];
    const int*   ei  = (const int*)d_in[1];      // int32 edge_index (JAX default)
    const float* W1  = (const float*)d_in[2];
    const float* b1  = (const float*)d_in[3];
    const float* g1  = (const float*)d_in[4];
    const float* be1 = (const float*)d_in[5];
    const float* W2  = (const float*)d_in[6];
    const float* b2  = (const float*)d_in[7];
    const float* g2  = (const float*)d_in[8];
    const float* be2 = (const float*)d_in[9];
    const float* W3  = (const float*)d_in[10];
    const float* b3  = (const float*)d_in[11];
    const float* Wl  = (const float*)d_in[12];
    const float* bl  = (const float*)d_in[13];
    float* out = (float*)d_out;

    int n = in_sizes[0] / INF;     // 50000
    int e = in_sizes[1] / 2;       // 800000
    int nb = (n + 1023) / 1024;    // scan blocks (49)

    k_init<<<(n + 255) / 256, 256>>>(n);
    k_deg<<<(e + 255) / 256, 256>>>(ei, e, n);
    k_scan1<<<nb, 1024>>>(n);
    k_scan2<<<1, 64>>>(nb);
    k_scan3<<<nb, 1024>>>(n);
    k_scatter<<<(e + 255) / 256, 256>>>(ei, e, n);

    // layer 1: aggregate-first (width 128), then TC GEMM (stats fused)
    k_aggX<<<n, 32>>>(x);
    dim3 gg((n + 127) / 128, 2);
    k_gemm256_tc<1><<<gg, 256>>>(W1, b1, n);
    k_bnparams<<<1, 256>>>(g1, be1, n);

    // layer 2: aggregate f1(m1) (width 256), then TC GEMM (stats fused)
    k_agg256<<<n, 64>>>();
    k_gemm256_tc<2><<<gg, 256>>>(W2, b2, n);
    k_bnparams<<<1, 256>>>(g2, be2, n);

    // layer 3: GEMM-first (f2 fused into A-load, dinv in epilogue), aggregate width 40
    k_gemm40<<<(n + 63) / 64, 256>>>(W3, n);
    k_agg40<<<(n + 7) / 8, 256>>>(b3, n);

    // final linear + log_softmax
    k_final<<<(n + 7) / 8, 256>>>(Wl, bl, out, n);
}

// round 10
// speedup vs baseline: 1.6227x; 1.2569x over previous
#include <cuda_runtime.h>
#include <cuda_fp16.h>
#include <math.h>
#include <stdint.h>

#define NN 50000
#define EE 800000
#define INF 128
#define HID 256
#define OUTD 40

// ---------------- scratch (static device globals; no allocation) -------------
// NOTE: relies on loader zero-init for g_deg / g_sumf / g_sum2f on first run;
// kernels self-reset them each launch for graph-replay determinism.
__device__ int    g_deg[NN];        // indeg (self-loop added analytically)
__device__ float  g_dinv[NN];
__device__ int    g_rowptr[NN + 1];
__device__ int    g_cursor[NN];
__device__ int    g_col[EE];
__device__ int    g_bsum[64];
__device__ __align__(16) __half g_xh[(size_t)NN * INF];    // x in fp16
__device__ __align__(16) __half g_aggxh[(size_t)NN * INF]; // Â x (fp16)
__device__ __align__(16) __half g_mh[(size_t)NN * HID];    // conv outputs m1/m2 (fp16)
__device__ __align__(16) __half g_aggh[(size_t)NN * HID];  // Â f1(m1) (fp16)
__device__ __align__(16) float  g_p3[(size_t)NN * OUTD];   // dinv*(f2(m2)@W3)
__device__ __align__(16) float  g_h3[(size_t)NN * OUTD];   // conv3 output
__device__ float  g_sumf[HID];     // fused BN stats (fp32, atomic)
__device__ float  g_sum2f[HID];
__device__ float  g_scale[HID];
__device__ float  g_shift[HID];

// ---------------- half pack/unpack helpers -------------------------------------
__device__ __forceinline__ void h4f(uint2 u, float f[4]) {
    float2 p0 = __half22float2(*(__half2*)&u.x);
    float2 p1 = __half22float2(*(__half2*)&u.y);
    f[0] = p0.x; f[1] = p0.y; f[2] = p1.x; f[3] = p1.y;
}
__device__ __forceinline__ uint2 f4h(const float f[4]) {
    __half2 h0 = __floats2half2_rn(f[0], f[1]);
    __half2 h1 = __floats2half2_rn(f[2], f[3]);
    uint2 u;
    u.x = *(uint32_t*)&h0;
    u.y = *(uint32_t*)&h1;
    return u;
}
__device__ __forceinline__ void h8f(uint4 u, float f[8]) {
    h4f(make_uint2(u.x, u.y), f);
    h4f(make_uint2(u.z, u.w), f + 4);
}
__device__ __forceinline__ uint4 f8h(const float f[8]) {
    uint2 a = f4h(f), b = f4h(f + 4);
    return make_uint4(a.x, a.y, b.x, b.y);
}

// ---------------- graph preprocessing ----------------------------------------
// in-degree only (g_deg zeroed by loader / previous scan23)
__global__ void k_deg(const int* __restrict__ ei, int e, int n) {
    int i = blockIdx.x * blockDim.x + threadIdx.x;
    if (i < e) {
        int d = ei[e + i];
        if ((unsigned)d < (unsigned)n) atomicAdd(&g_deg[d], 1);
    }
}

// phase 1: per-block inclusive scan of indeg; dinv = rsqrt(indeg+1)
__global__ __launch_bounds__(1024) void k_scan1(int n) {
    __shared__ int warpsums[32];
    int b = blockIdx.x, tid = threadIdx.x;
    int i = b * 1024 + tid;
    int v = 0;
    if (i < n) {
        int d = g_deg[i];
        v = d;
        g_dinv[i] = rsqrtf((float)(d + 1));
    }
    int x = v;
    #pragma unroll
    for (int o = 1; o < 32; o <<= 1) {
        int y = __shfl_up_sync(0xFFFFFFFFu, x, o);
        if ((tid & 31) >= o) x += y;
    }
    if ((tid & 31) == 31) warpsums[tid >> 5] = x;
    __syncthreads();
    if (tid < 32) {
        int w = warpsums[tid];
        #pragma unroll
        for (int o = 1; o < 32; o <<= 1) {
            int y = __shfl_up_sync(0xFFFFFFFFu, w, o);
            if (tid >= o) w += y;
        }
        warpsums[tid] = w;
    }
    __syncthreads();
    int incl = x + ((tid >= 32) ? warpsums[(tid >> 5) - 1] : 0);
    if (i < n) g_rowptr[i + 1] = incl;              // local inclusive
    if (tid == 1023) g_bsum[b] = incl;              // block total
}

// phase 2+3 merged: each block redundantly scans the <=64 block totals,
// picks its own offset, finalizes rowptr+cursor, resets g_deg.
__global__ __launch_bounds__(1024) void k_scan23(int n, int nb) {
    __shared__ int w0s;
    __shared__ int s_off;
    int tid = threadIdx.x;
    int v = 0, x = 0;
    if (tid < 64) {
        v = (tid < nb) ? g_bsum[tid] : 0;
        x = v;
        #pragma unroll
        for (int o = 1; o < 32; o <<= 1) {
            int y = __shfl_up_sync(0xFFFFFFFFu, x, o);
            if ((tid & 31) >= o) x += y;
        }
        if (tid == 31) w0s = x;
    }
    __syncthreads();
    if (tid < 64) {
        int incl = x + ((tid >= 32) ? w0s : 0);
        if (tid == blockIdx.x) s_off = incl - v;    // exclusive prefix for this block
    }
    __syncthreads();
    int i = blockIdx.x * 1024 + tid;
    if (i < n) {
        int indeg = g_deg[i];
        int val = g_rowptr[i + 1] + s_off;
        g_rowptr[i + 1] = val;
        g_cursor[i] = val - indeg;
        g_deg[i] = 0;                               // reset for next replay
    }
    if (i == 0) g_rowptr[0] = 0;
}

__global__ void k_scatter(const int* __restrict__ ei, int e, int n) {
    int i = blockIdx.x * blockDim.x + threadIdx.x;
    if (i < e) {
        int s = ei[i], d = ei[e + i];
        if ((unsigned)d < (unsigned)n) {
            s = min(max(s, 0), n - 1);              // clamp keeps CSR hole-free
            int pos = atomicAdd(&g_cursor[d], 1);
            g_col[pos] = s;
        }
    }
}

// ---------------- x -> fp16 -----------------------------------------------------
__global__ void k_xtoh(const float* __restrict__ x, int total8) {
    int i = blockIdx.x * blockDim.x + threadIdx.x;
    if (i < total8) {
        float4 a = ((const float4*)x)[i * 2];
        float4 b = ((const float4*)x)[i * 2 + 1];
        float f[8] = {a.x, a.y, a.z, a.w, b.x, b.y, b.z, b.w};
        ((uint4*)g_xh)[i] = f8h(f);
    }
}

// ---------------- aggregation kernels (fp16 gather) -----------------------------
// g_aggxh[i] = dinv[i] * ( dinv[i]*x[i] + sum_{s in N(i)} dinv[s]*x[s] )
__global__ void k_aggX() {
    int i = blockIdx.x, t = threadIdx.x;  // 32 threads, 4 halves each (128)
    const uint2* __restrict__ x2 = (const uint2*)g_xh;   // 32 uint2 per row
    float di = g_dinv[i];
    float acc[4], f[4];
    h4f(x2[(size_t)i * 32 + t], f);
    #pragma unroll
    for (int j = 0; j < 4; j++) acc[j] = di * f[j];
    int e0 = g_rowptr[i], e1 = g_rowptr[i + 1];
    int e = e0;
    for (; e + 1 < e1; e += 2) {
        int s0 = g_col[e], s1 = g_col[e + 1];
        float d0 = g_dinv[s0], d1 = g_dinv[s1];
        float f0[4], f1[4];
        h4f(x2[(size_t)s0 * 32 + t], f0);
        h4f(x2[(size_t)s1 * 32 + t], f1);
        #pragma unroll
        for (int j = 0; j < 4; j++) acc[j] += d0 * f0[j] + d1 * f1[j];
    }
    if (e < e1) {
        int s = g_col[e];
        float d = g_dinv[s];
        h4f(x2[(size_t)s * 32 + t], f);
        #pragma unroll
        for (int j = 0; j < 4; j++) acc[j] += d * f[j];
    }
    #pragma unroll
    for (int j = 0; j < 4; j++) acc[j] *= di;
    ((uint2*)g_aggxh)[(size_t)i * 32 + t] = f4h(acc);
}

// g_aggh[i] = dinv[i] * ( dinv[i]*f(m[i]) + sum dinv[s]*f(m[s]) ), f=relu(affine)
__global__ void k_agg256() {
    int i = blockIdx.x, t = threadIdx.x;  // 32 threads, 8 halves each (256)
    const uint4* __restrict__ m4 = (const uint4*)g_mh;   // 32 uint4 per row
    float sc[8], sh[8];
    {
        float4 s0 = ((const float4*)g_scale)[2 * t];
        float4 s1 = ((const float4*)g_scale)[2 * t + 1];
        float4 h0 = ((const float4*)g_shift)[2 * t];
        float4 h1 = ((const float4*)g_shift)[2 * t + 1];
        sc[0]=s0.x; sc[1]=s0.y; sc[2]=s0.z; sc[3]=s0.w;
        sc[4]=s1.x; sc[5]=s1.y; sc[6]=s1.z; sc[7]=s1.w;
        sh[0]=h0.x; sh[1]=h0.y; sh[2]=h0.z; sh[3]=h0.w;
        sh[4]=h1.x; sh[5]=h1.y; sh[6]=h1.z; sh[7]=h1.w;
    }
    float di = g_dinv[i];
    float acc[8], f[8];
    h8f(m4[(size_t)i * 32 + t], f);
    #pragma unroll
    for (int j = 0; j < 8; j++)
        acc[j] = di * fmaxf(fmaf(f[j], sc[j], sh[j]), 0.f);
    int e0 = g_rowptr[i], e1 = g_rowptr[i + 1];
    int e = e0;
    for (; e + 1 < e1; e += 2) {
        int s0 = g_col[e], s1 = g_col[e + 1];
        float d0 = g_dinv[s0], d1 = g_dinv[s1];
        float f0[8], f1[8];
        h8f(m4[(size_t)s0 * 32 + t], f0);
        h8f(m4[(size_t)s1 * 32 + t], f1);
        #pragma unroll
        for (int j = 0; j < 8; j++)
            acc[j] += d0 * fmaxf(fmaf(f0[j], sc[j], sh[j]), 0.f)
                    + d1 * fmaxf(fmaf(f1[j], sc[j], sh[j]), 0.f);
    }
    if (e < e1) {
        int s = g_col[e];
        float d = g_dinv[s];
        h8f(m4[(size_t)s * 32 + t], f);
        #pragma unroll
        for (int j = 0; j < 8; j++)
            acc[j] += d * fmaxf(fmaf(f[j], sc[j], sh[j]), 0.f);
    }
    #pragma unroll
    for (int j = 0; j < 8; j++) acc[j] *= di;
    ((uint4*)g_aggh)[(size_t)i * 32 + t] = f8h(acc);
}

// g_h3[i] = dinv[i]*(p3[i] + sum p3[s]) + b3   (p3 fp32; dinv[src] folded)
__global__ void k_agg40(const float* __restrict__ b3, int n) {
    int node = blockIdx.x * 8 + (threadIdx.x >> 5);
    int lane = threadIdx.x & 31;
    if (node >= n || lane >= 10) return;
    const float4* __restrict__ p4 = (const float4*)g_p3;
    float4 acc = p4[(size_t)node * 10 + lane];
    int e0 = g_rowptr[node], e1 = g_rowptr[node + 1];
    int e = e0;
    for (; e + 1 < e1; e += 2) {
        int s0 = g_col[e], s1 = g_col[e + 1];
        float4 v0 = p4[(size_t)s0 * 10 + lane];
        float4 v1 = p4[(size_t)s1 * 10 + lane];
        acc.x += v0.x + v1.x; acc.y += v0.y + v1.y;
        acc.z += v0.z + v1.z; acc.w += v0.w + v1.w;
    }
    if (e < e1) {
        float4 v0 = p4[(size_t)g_col[e] * 10 + lane];
        acc.x += v0.x; acc.y += v0.y; acc.z += v0.z; acc.w += v0.w;
    }
    float di = g_dinv[node];
    float4 bv = ((const float4*)b3)[lane];
    ((float4*)g_h3)[(size_t)node * 10 + lane] =
        make_float4(acc.x * di + bv.x, acc.y * di + bv.y,
                    acc.z * di + bv.z, acc.w * di + bv.w);
}

// ---------------- tensor-core GEMM: fp16 A (exact tf32), split-fp32 B ----------
// C_half[M,256] = A_half[M,K] @ B_f32[K,256] + bias ; BN stats fused.
__device__ __forceinline__ uint32_t f2tf32(float x) {
    uint32_t r;
    asm("cvt.rna.tf32.f32 %0, %1;" : "=r"(r) : "f"(x));
    return r;
}

__device__ __forceinline__ void mma_tf32(float c[4], const uint32_t a[4], const uint32_t b[2]) {
    asm volatile(
        "mma.sync.aligned.m16n8k8.row.col.f32.tf32.tf32.f32 "
        "{%0,%1,%2,%3}, {%4,%5,%6,%7}, {%8,%9}, {%0,%1,%2,%3};"
        : "+f"(c[0]), "+f"(c[1]), "+f"(c[2]), "+f"(c[3])
        : "r"(a[0]), "r"(a[1]), "r"(a[2]), "r"(a[3]), "r"(b[0]), "r"(b[1]));
}

#define TPAD 136  // stride: 136 % 32 == 8 -> conflict-free fragment loads

template <int LAYER>
__global__ __launch_bounds__(256) void k_gemm256_tc(
    const float* __restrict__ B, const float* __restrict__ bias, int M) {
    constexpr int K = (LAYER == 1) ? INF : HID;
    const __half* __restrict__ A = (LAYER == 1) ? g_aggxh : g_aggh;
    __half* __restrict__ C = g_mh;

    __shared__ uint32_t Ah[16][TPAD];
    __shared__ uint32_t Bh[16][TPAD], Bl[16][TPAD];
    __shared__ float s_s[128], s_s2[128];

    int t = threadIdx.x;
    int warp = t >> 5, lane = t & 31;
    int lr = lane >> 2, lc = lane & 3;
    int warpM = (warp >> 2) * 64;
    int warpN = (warp & 3) * 32;
    int rowBase = blockIdx.x * 128;
    int colBase = blockIdx.y * 128;

    if (t < 128) { s_s[t] = 0.f; s_s2[t] = 0.f; }

    float acc[4][4][4];
    #pragma unroll
    for (int mt = 0; mt < 4; mt++)
        #pragma unroll
        for (int nt = 0; nt < 4; nt++)
            #pragma unroll
            for (int j = 0; j < 4; j++) acc[mt][nt][j] = 0.f;

    for (int kk = 0; kk < K; kk += 16) {
        // A fill: 128 rows x 16 k halves; one uint4 (8 halves) per thread.
        // fp16 -> fp32 is exact and already tf32-representable: store raw bits.
        {
            int row = t >> 1, k8 = (t & 1) << 3;
            int r = rowBase + row;
            uint4 u = make_uint4(0, 0, 0, 0);
            if (r < M) u = *(const uint4*)(A + (size_t)r * K + kk + k8);
            __half2* hp = (__half2*)&u;
            #pragma unroll
            for (int j = 0; j < 4; j++) {
                float2 p = __half22float2(hp[j]);
                Ah[k8 + 2 * j][row]     = __float_as_uint(p.x);
                Ah[k8 + 2 * j + 1][row] = __float_as_uint(p.y);
            }
        }
        // B fill: 16 k-rows x 128 cols fp32, split hi/lo
        #pragma unroll
        for (int s = t; s < 512; s += 256) {
            int kr = s >> 5;
            int n4 = (s & 31) << 2;
            float4 v = *(const float4*)(B + (size_t)(kk + kr) * 256 + colBase + n4);
            float f[4] = {v.x, v.y, v.z, v.w};
            uint4 hb, lb;
            uint32_t* hp = (uint32_t*)&hb;
            uint32_t* lp = (uint32_t*)&lb;
            #pragma unroll
            for (int j = 0; j < 4; j++) {
                uint32_t hi = f2tf32(f[j]);
                hp[j] = hi;
                lp[j] = f2tf32(f[j] - __uint_as_float(hi));
            }
            *(uint4*)&Bh[kr][n4] = hb;
            *(uint4*)&Bl[kr][n4] = lb;
        }
        __syncthreads();

        #pragma unroll
        for (int s = 0; s < 2; s++) {
            int kc = s * 8;
            uint32_t ah[4][4], bh[4][2], bl[4][2];
            #pragma unroll
            for (int nt = 0; nt < 4; nt++) {
                int nc = warpN + nt * 8 + lr;
                bh[nt][0] = Bh[kc + lc][nc];
                bh[nt][1] = Bh[kc + 4 + lc][nc];
                bl[nt][0] = Bl[kc + lc][nc];
                bl[nt][1] = Bl[kc + 4 + lc][nc];
            }
            #pragma unroll
            for (int mt = 0; mt < 4; mt++) {
                int m = warpM + mt * 16 + lr;
                ah[mt][0] = Ah[kc + lc][m];
                ah[mt][1] = Ah[kc + lc][m + 8];
                ah[mt][2] = Ah[kc + 4 + lc][m];
                ah[mt][3] = Ah[kc + 4 + lc][m + 8];
            }
            #pragma unroll
            for (int mt = 0; mt < 4; mt++)
                #pragma unroll
                for (int nt = 0; nt < 4; nt++) {
                    mma_tf32(acc[mt][nt], ah[mt], bh[nt]);   // A * B_hi
                    mma_tf32(acc[mt][nt], ah[mt], bl[nt]);   // A * B_lo
                }
        }
        __syncthreads();
    }

    // epilogue: bias add + half store + fused BN-stat accumulation (fp32)
    float ls[8], ls2[8];
    #pragma unroll
    for (int j = 0; j < 8; j++) { ls[j] = 0.f; ls2[j] = 0.f; }

    #pragma unroll
    for (int nt = 0; nt < 4; nt++) {
        int col = colBase + warpN + nt * 8 + 2 * lc;
        float b0 = bias[col], b1 = bias[col + 1];
        #pragma unroll
        for (int mt = 0; mt < 4; mt++) {
            int r0 = rowBase + warpM + mt * 16 + lr;
            if (r0 < M) {
                float o0 = acc[mt][nt][0] + b0, o1 = acc[mt][nt][1] + b1;
                *(__half2*)(C + (size_t)r0 * 256 + col) = __floats2half2_rn(o0, o1);
                ls[nt * 2]     += o0;  ls2[nt * 2]     = fmaf(o0, o0, ls2[nt * 2]);
                ls[nt * 2 + 1] += o1;  ls2[nt * 2 + 1] = fmaf(o1, o1, ls2[nt * 2 + 1]);
            }
            int r1 = r0 + 8;
            if (r1 < M) {
                float o2 = acc[mt][nt][2] + b0, o3 = acc[mt][nt][3] + b1;
                *(__half2*)(C + (size_t)r1 * 256 + col) = __floats2half2_rn(o2, o3);
                ls[nt * 2]     += o2;  ls2[nt * 2]     = fmaf(o2, o2, ls2[nt * 2]);
                ls[nt * 2 + 1] += o3;  ls2[nt * 2 + 1] = fmaf(o3, o3, ls2[nt * 2 + 1]);
            }
        }
    }
    __syncthreads();
    #pragma unroll
    for (int nt = 0; nt < 4; nt++) {
        int c0 = warpN + nt * 8 + 2 * lc;
        atomicAdd(&s_s[c0],      ls[nt * 2]);
        atomicAdd(&s_s2[c0],     ls2[nt * 2]);
        atomicAdd(&s_s[c0 + 1],  ls[nt * 2 + 1]);
        atomicAdd(&s_s2[c0 + 1], ls2[nt * 2 + 1]);
    }
    __syncthreads();
    if (t < 128) {
        atomicAdd(&g_sumf[colBase + t],  s_s[t]);
        atomicAdd(&g_sum2f[colBase + t], s_s2[t]);
    }
}

// ---------------- GEMM: g_p3[M,40] = dinv * ( f2(g_mh)[M,256] @ W3[256,40] ) --
__global__ __launch_bounds__(256) void k_gemm40(
    const float* __restrict__ W, int M) {
    const __half* __restrict__ A = g_mh;
    __shared__ float As[32][65];
    __shared__ float Ws[32][40];
    __shared__ float ssc[HID], ssh[HID];
    int tid = threadIdx.x;
    ssc[tid] = g_scale[tid];
    ssh[tid] = g_shift[tid];
    __syncthreads();

    int rowBase = blockIdx.x * 64;
    int r = tid & 63;
    int cg = tid >> 6;  // 0..3 -> cols cg*10..cg*10+9
    float acc[10];
    #pragma unroll
    for (int j = 0; j < 10; j++) acc[j] = 0.f;

    int aRow = tid >> 3;        // 0..31
    int aCol = (tid & 7) << 2;  // 0..28

    for (int kk = 0; kk < HID; kk += 32) {
        #pragma unroll
        for (int rr = 0; rr < 2; rr++) {
            int row = rowBase + aRow + rr * 32;
            float v[4] = {0.f, 0.f, 0.f, 0.f};
            if (row < M) {
                uint2 u = *(const uint2*)(A + (size_t)row * HID + kk + aCol);
                h4f(u, v);
            }
            int c = kk + aCol;
            #pragma unroll
            for (int j = 0; j < 4; j++)
                As[aCol + j][aRow + rr * 32] =
                    fmaxf(fmaf(v[j], ssc[c + j], ssh[c + j]), 0.f);
        }
        for (int idx = tid; idx < 32 * OUTD; idx += 256) {
            int kr = idx / OUTD, c = idx % OUTD;
            Ws[kr][c] = W[(size_t)(kk + kr) * OUTD + c];
        }
        __syncthreads();
        #pragma unroll
        for (int k = 0; k < 32; k++) {
            float a = As[k][r];
            #pragma unroll
            for (int j = 0; j < 10; j++)
                acc[j] = fmaf(a, Ws[k][cg * 10 + j], acc[j]);
        }
        __syncthreads();
    }
    int row = rowBase + r;
    if (row < M) {
        float d = g_dinv[row];
        #pragma unroll
        for (int j = 0; j < 10; j++)
            g_p3[(size_t)row * OUTD + cg * 10 + j] = acc[j] * d;
    }
}

// ---------------- BN params from fused stats -----------------------------------
__global__ void k_bnparams(const float* __restrict__ g, const float* __restrict__ be, int n) {
    int t = threadIdx.x;  // 256
    float s = g_sumf[t], s2 = g_sum2f[t];
    g_sumf[t] = 0.f;
    g_sum2f[t] = 0.f;
    float inv_n = 1.f / (float)n;
    float mean = s * inv_n;
    float var  = fmaf(s2, inv_n, -mean * mean);
    float rs = rsqrtf(var + 1e-5f);
    float sc = rs * g[t];
    g_scale[t] = sc;
    g_shift[t] = be[t] - mean * sc;
}

// ---------------- final: out = log_softmax(g_h3 @ Wl + bl) ---------------------
__global__ void k_final(const float* __restrict__ Wl, const float* __restrict__ bl,
                        float* __restrict__ out, int n) {
    __shared__ float sW[OUTD * OUTD];
    __shared__ float sb[OUTD];
    int tid = threadIdx.x;  // 256
    for (int i = tid; i < OUTD * OUTD; i += 256) sW[i] = Wl[i];
    if (tid < OUTD) sb[tid] = bl[tid];
    __syncthreads();
    int warp = tid >> 5, lane = tid & 31;
    int row = blockIdx.x * 8 + warp;
    if (row >= n) return;
    const float* a = g_h3 + (size_t)row * OUTD;
    float a_lo = a[lane];
    float a_hi = (lane < 8) ? a[32 + lane] : 0.f;
    float z0 = sb[lane];
    float z1 = (lane < 8) ? sb[32 + lane] : -1e30f;
    #pragma unroll
    for (int k = 0; k < OUTD; k++) {
        float ak = (k < 32) ? __shfl_sync(0xFFFFFFFFu, a_lo, k)
                            : __shfl_sync(0xFFFFFFFFu, a_hi, k - 32);
        z0 = fmaf(ak, sW[k * OUTD + lane], z0);
        if (lane < 8) z1 = fmaf(ak, sW[k * OUTD + 32 + lane], z1);
    }
    float mx = fmaxf(z0, z1);
    #pragma unroll
    for (int o = 16; o; o >>= 1) mx = fmaxf(mx, __shfl_xor_sync(0xFFFFFFFFu, mx, o));
    float es = expf(z0 - mx) + ((lane < 8) ? expf(z1 - mx) : 0.f);
    #pragma unroll
    for (int o = 16; o; o >>= 1) es += __shfl_xor_sync(0xFFFFFFFFu, es, o);
    float L = mx + logf(es);
    out[(size_t)row * OUTD + lane] = z0 - L;
    if (lane < 8) out[(size_t)row * OUTD + 32 + lane] = z1 - L;
}

// ---------------- launch (kernel launches ONLY — no CUDA API calls) ------------
extern "C" void kernel_launch(void* const* d_in, const int* in_sizes, int n_in,
                              void* d_out, int out_size) {
    const float* x   = (const float*)d_in[0];
    const int*   ei  = (const int*)d_in[1];      // int32 edge_index (JAX default)
    const float* W1  = (const float*)d_in[2];
    const float* b1  = (const float*)d_in[3];
    const float* g1  = (const float*)d_in[4];
    const float* be1 = (const float*)d_in[5];
    const float* W2  = (const float*)d_in[6];
    const float* b2  = (const float*)d_in[7];
    const float* g2  = (const float*)d_in[8];
    const float* be2 = (const float*)d_in[9];
    const float* W3  = (const float*)d_in[10];
    const float* b3  = (const float*)d_in[11];
    const float* Wl  = (const float*)d_in[12];
    const float* bl  = (const float*)d_in[13];
    float* out = (float*)d_out;

    int n = in_sizes[0] / INF;     // 50000
    int e = in_sizes[1] / 2;       // 800000
    int nb = (n + 1023) / 1024;    // scan blocks (49)

    k_deg<<<(e + 255) / 256, 256>>>(ei, e, n);
    k_scan1<<<nb, 1024>>>(n);
    k_scan23<<<nb, 1024>>>(n, nb);
    k_scatter<<<(e + 255) / 256, 256>>>(ei, e, n);
    int total8 = n * INF / 8;
    k_xtoh<<<(total8 + 255) / 256, 256>>>(x, total8);

    // layer 1: aggregate-first (width 128 fp16), then TC GEMM (stats fused)
    k_aggX<<<n, 32>>>();
    dim3 gg((n + 127) / 128, 2);
    k_gemm256_tc<1><<<gg, 256>>>(W1, b1, n);
    k_bnparams<<<1, 256>>>(g1, be1, n);

    // layer 2: aggregate f1(m1) (width 256 fp16), then TC GEMM (stats fused)
    k_agg256<<<n, 32>>>();
    k_gemm256_tc<2><<<gg, 256>>>(W2, b2, n);
    k_bnparams<<<1, 256>>>(g2, be2, n);

    // layer 3: GEMM-first (f2 fused into A-load, dinv in epilogue), aggregate width 40
    k_gemm40<<<(n + 63) / 64, 256>>>(W3, n);
    k_agg40<<<(n + 7) / 8, 256>>>(b3, n);

    // final linear + log_softmax
    k_final<<<(n + 7) / 8, 256>>>(Wl, bl, out, n);
}

// round 13
// speedup vs baseline: 2.1154x; 1.3037x over previous
#include <cuda_runtime.h>
#include <cuda_fp16.h>
#include <math.h>
#include <stdint.h>

#define NN 50000
#define EE 800000
#define INF 128
#define HID 256
#define OUTD 40

// ---------------- scratch (static device globals; no allocation) -------------
__device__ int    g_deg[NN];        // indeg (self-loop added analytically)
__device__ float  g_dinv[NN];
__device__ int    g_rowptr[NN + 1];
__device__ int    g_cursor[NN];
__device__ int    g_col[EE];
__device__ int    g_bsum[64];
__device__ __align__(16) __half g_xh[(size_t)NN * INF];    // x in fp16
__device__ __align__(16) __half g_aggxh[(size_t)NN * INF]; // Â x (fp16)
__device__ __align__(16) __half g_mh[(size_t)NN * HID];    // conv outputs m1/m2 (fp16)
__device__ __align__(16) __half g_aggh[(size_t)NN * HID];  // Â f1(m1) (fp16)
__device__ __align__(16) float  g_p3[(size_t)NN * OUTD];   // dinv*(f2(m2)@W3)
__device__ __align__(16) float  g_h3[(size_t)NN * OUTD];   // conv3 output
__device__ float  g_sumf[HID];     // fused BN stats (fp32, atomic)
__device__ float  g_sum2f[HID];
__device__ float  g_scale[HID];
__device__ float  g_shift[HID];

// ---------------- half pack/unpack helpers -------------------------------------
__device__ __forceinline__ void h4f(uint2 u, float f[4]) {
    float2 p0 = __half22float2(*(__half2*)&u.x);
    float2 p1 = __half22float2(*(__half2*)&u.y);
    f[0] = p0.x; f[1] = p0.y; f[2] = p1.x; f[3] = p1.y;
}
__device__ __forceinline__ uint2 f4h(const float f[4]) {
    __half2 h0 = __floats2half2_rn(f[0], f[1]);
    __half2 h1 = __floats2half2_rn(f[2], f[3]);
    uint2 u;
    u.x = *(uint32_t*)&h0;
    u.y = *(uint32_t*)&h1;
    return u;
}
__device__ __forceinline__ void h8f(uint4 u, float f[8]) {
    h4f(make_uint2(u.x, u.y), f);
    h4f(make_uint2(u.z, u.w), f + 4);
}
__device__ __forceinline__ uint4 f8h(const float f[8]) {
    uint2 a = f4h(f), b = f4h(f + 4);
    return make_uint4(a.x, a.y, b.x, b.y);
}
__device__ __forceinline__ uint32_t pack2h(float a, float b) {
    __half2 h = __floats2half2_rn(a, b);
    return *(uint32_t*)&h;
}

// ---------------- graph preprocessing ----------------------------------------
__global__ void k_deg(const int* __restrict__ ei, int e, int n) {
    int i = blockIdx.x * blockDim.x + threadIdx.x;
    if (i < e) {
        int d = ei[e + i];
        if ((unsigned)d < (unsigned)n) atomicAdd(&g_deg[d], 1);
    }
}

// phase 1: per-block inclusive scan of indeg; dinv = rsqrt(indeg+1)
__global__ __launch_bounds__(1024) void k_scan1(int n) {
    __shared__ int warpsums[32];
    int b = blockIdx.x, tid = threadIdx.x;
    int i = b * 1024 + tid;
    int v = 0;
    if (i < n) {
        int d = g_deg[i];
        v = d;
        g_dinv[i] = rsqrtf((float)(d + 1));
    }
    int x = v;
    #pragma unroll
    for (int o = 1; o < 32; o <<= 1) {
        int y = __shfl_up_sync(0xFFFFFFFFu, x, o);
        if ((tid & 31) >= o) x += y;
    }
    if ((tid & 31) == 31) warpsums[tid >> 5] = x;
    __syncthreads();
    if (tid < 32) {
        int w = warpsums[tid];
        #pragma unroll
        for (int o = 1; o < 32; o <<= 1) {
            int y = __shfl_up_sync(0xFFFFFFFFu, w, o);
            if (tid >= o) w += y;
        }
        warpsums[tid] = w;
    }
    __syncthreads();
    int incl = x + ((tid >= 32) ? warpsums[(tid >> 5) - 1] : 0);
    if (i < n) g_rowptr[i + 1] = incl;
    if (tid == 1023) g_bsum[b] = incl;
}

// phase 2+3 merged: each block redundantly scans block totals, applies offset
__global__ __launch_bounds__(1024) void k_scan23(int n, int nb) {
    __shared__ int w0s;
    __shared__ int s_off;
    int tid = threadIdx.x;
    int v = 0, x = 0;
    if (tid < 64) {
        v = (tid < nb) ? g_bsum[tid] : 0;
        x = v;
        #pragma unroll
        for (int o = 1; o < 32; o <<= 1) {
            int y = __shfl_up_sync(0xFFFFFFFFu, x, o);
            if ((tid & 31) >= o) x += y;
        }
        if (tid == 31) w0s = x;
    }
    __syncthreads();
    if (tid < 64) {
        int incl = x + ((tid >= 32) ? w0s : 0);
        if (tid == blockIdx.x) s_off = incl - v;
    }
    __syncthreads();
    int i = blockIdx.x * 1024 + tid;
    if (i < n) {
        int indeg = g_deg[i];
        int val = g_rowptr[i + 1] + s_off;
        g_rowptr[i + 1] = val;
        g_cursor[i] = val - indeg;
        g_deg[i] = 0;                               // reset for next replay
    }
    if (i == 0) g_rowptr[0] = 0;
}

__global__ void k_scatter(const int* __restrict__ ei, int e, int n) {
    int i = blockIdx.x * blockDim.x + threadIdx.x;
    if (i < e) {
        int s = ei[i], d = ei[e + i];
        if ((unsigned)d < (unsigned)n) {
            s = min(max(s, 0), n - 1);
            int pos = atomicAdd(&g_cursor[d], 1);
            g_col[pos] = s;
        }
    }
}

// ---------------- x -> fp16 -----------------------------------------------------
__global__ void k_xtoh(const float* __restrict__ x, int total8) {
    int i = blockIdx.x * blockDim.x + threadIdx.x;
    if (i < total8) {
        float4 a = ((const float4*)x)[i * 2];
        float4 b = ((const float4*)x)[i * 2 + 1];
        float f[8] = {a.x, a.y, a.z, a.w, b.x, b.y, b.z, b.w};
        ((uint4*)g_xh)[i] = f8h(f);
    }
}

// ---------------- aggregation kernels (fp16 gather) -----------------------------
__global__ void k_aggX() {
    int i = blockIdx.x, t = threadIdx.x;  // 32 threads, 4 halves each (128)
    const uint2* __restrict__ x2 = (const uint2*)g_xh;
    float di = g_dinv[i];
    float acc[4], f[4];
    h4f(x2[(size_t)i * 32 + t], f);
    #pragma unroll
    for (int j = 0; j < 4; j++) acc[j] = di * f[j];
    int e0 = g_rowptr[i], e1 = g_rowptr[i + 1];
    int e = e0;
    for (; e + 1 < e1; e += 2) {
        int s0 = g_col[e], s1 = g_col[e + 1];
        float d0 = g_dinv[s0], d1 = g_dinv[s1];
        float f0[4], f1[4];
        h4f(x2[(size_t)s0 * 32 + t], f0);
        h4f(x2[(size_t)s1 * 32 + t], f1);
        #pragma unroll
        for (int j = 0; j < 4; j++) acc[j] += d0 * f0[j] + d1 * f1[j];
    }
    if (e < e1) {
        int s = g_col[e];
        float d = g_dinv[s];
        h4f(x2[(size_t)s * 32 + t], f);
        #pragma unroll
        for (int j = 0; j < 4; j++) acc[j] += d * f[j];
    }
    #pragma unroll
    for (int j = 0; j < 4; j++) acc[j] *= di;
    ((uint2*)g_aggxh)[(size_t)i * 32 + t] = f4h(acc);
}

__global__ void k_agg256() {
    int i = blockIdx.x, t = threadIdx.x;  // 32 threads, 8 halves each (256)
    const uint4* __restrict__ m4 = (const uint4*)g_mh;
    float sc[8], sh[8];
    {
        float4 s0 = ((const float4*)g_scale)[2 * t];
        float4 s1 = ((const float4*)g_scale)[2 * t + 1];
        float4 h0 = ((const float4*)g_shift)[2 * t];
        float4 h1 = ((const float4*)g_shift)[2 * t + 1];
        sc[0]=s0.x; sc[1]=s0.y; sc[2]=s0.z; sc[3]=s0.w;
        sc[4]=s1.x; sc[5]=s1.y; sc[6]=s1.z; sc[7]=s1.w;
        sh[0]=h0.x; sh[1]=h0.y; sh[2]=h0.z; sh[3]=h0.w;
        sh[4]=h1.x; sh[5]=h1.y; sh[6]=h1.z; sh[7]=h1.w;
    }
    float di = g_dinv[i];
    float acc[8], f[8];
    h8f(m4[(size_t)i * 32 + t], f);
    #pragma unroll
    for (int j = 0; j < 8; j++)
        acc[j] = di * fmaxf(fmaf(f[j], sc[j], sh[j]), 0.f);
    int e0 = g_rowptr[i], e1 = g_rowptr[i + 1];
    int e = e0;
    for (; e + 1 < e1; e += 2) {
        int s0 = g_col[e], s1 = g_col[e + 1];
        float d0 = g_dinv[s0], d1 = g_dinv[s1];
        float f0[8], f1[8];
        h8f(m4[(size_t)s0 * 32 + t], f0);
        h8f(m4[(size_t)s1 * 32 + t], f1);
        #pragma unroll
        for (int j = 0; j < 8; j++)
            acc[j] += d0 * fmaxf(fmaf(f0[j], sc[j], sh[j]), 0.f)
                    + d1 * fmaxf(fmaf(f1[j], sc[j], sh[j]), 0.f);
    }
    if (e < e1) {
        int s = g_col[e];
        float d = g_dinv[s];
        h8f(m4[(size_t)s * 32 + t], f);
        #pragma unroll
        for (int j = 0; j < 8; j++)
            acc[j] += d * fmaxf(fmaf(f[j], sc[j], sh[j]), 0.f);
    }
    #pragma unroll
    for (int j = 0; j < 8; j++) acc[j] *= di;
    ((uint4*)g_aggh)[(size_t)i * 32 + t] = f8h(acc);
}

__global__ void k_agg40(const float* __restrict__ b3, int n) {
    int node = blockIdx.x * 8 + (threadIdx.x >> 5);
    int lane = threadIdx.x & 31;
    if (node >= n || lane >= 10) return;
    const float4* __restrict__ p4 = (const float4*)g_p3;
    float4 acc = p4[(size_t)node * 10 + lane];
    int e0 = g_rowptr[node], e1 = g_rowptr[node + 1];
    int e = e0;
    for (; e + 1 < e1; e += 2) {
        int s0 = g_col[e], s1 = g_col[e + 1];
        float4 v0 = p4[(size_t)s0 * 10 + lane];
        float4 v1 = p4[(size_t)s1 * 10 + lane];
        acc.x += v0.x + v1.x; acc.y += v0.y + v1.y;
        acc.z += v0.z + v1.z; acc.w += v0.w + v1.w;
    }
    if (e < e1) {
        float4 v0 = p4[(size_t)g_col[e] * 10 + lane];
        acc.x += v0.x; acc.y += v0.y; acc.z += v0.z; acc.w += v0.w;
    }
    float di = g_dinv[node];
    float4 bv = ((const float4*)b3)[lane];
    ((float4*)g_h3)[(size_t)node * 10 + lane] =
        make_float4(acc.x * di + bv.x, acc.y * di + bv.y,
                    acc.z * di + bv.z, acc.w * di + bv.w);
}

// ---------------- fp16 m16n8k16 MMA helper --------------------------------------
__device__ __forceinline__ void mma_f16(float c[4], const uint32_t a[4], const uint32_t b[2]) {
    asm volatile(
        "mma.sync.aligned.m16n8k16.row.col.f32.f16.f16.f32 "
        "{%0,%1,%2,%3}, {%4,%5,%6,%7}, {%8,%9}, {%0,%1,%2,%3};"
        : "+f"(c[0]), "+f"(c[1]), "+f"(c[2]), "+f"(c[3])
        : "r"(a[0]), "r"(a[1]), "r"(a[2]), "r"(a[3]), "r"(b[0]), "r"(b[1]));
}

#define TPAD 136  // word stride: 136 % 32 == 8 -> conflict-free fragment loads

// ---------------- fp16 TC GEMM: C_h[M,256] = A_h[M,K] @ B_f32h[K,256] + bias ---
// K-step 32 (= 2 x k16). A exact fp16; B rounded to fp16. BN stats fused.
template <int LAYER>
__global__ __launch_bounds__(256) void k_gemm256_tc(
    const float* __restrict__ B, const float* __restrict__ bias, int M) {
    constexpr int K = (LAYER == 1) ? INF : HID;
    const __half* __restrict__ A = (LAYER == 1) ? g_aggxh : g_aggh;
    __half* __restrict__ C = g_mh;

    __shared__ uint32_t As2[16][TPAD];   // [k2 within 32-k step][m]  half2 words
    __shared__ uint32_t Bs2[16][TPAD];   // [k2][n]                   half2 words
    __shared__ float s_s[128], s_s2[128];

    int t = threadIdx.x;
    int warp = t >> 5, lane = t & 31;
    int lr = lane >> 2, lc = lane & 3;
    int warpM = (warp >> 2) * 64;
    int warpN = (warp & 3) * 32;
    int rowBase = blockIdx.x * 128;
    int colBase = blockIdx.y * 128;

    if (t < 128) { s_s[t] = 0.f; s_s2[t] = 0.f; }

    float acc[4][4][4];
    #pragma unroll
    for (int mt = 0; mt < 4; mt++)
        #pragma unroll
        for (int nt = 0; nt < 4; nt++)
            #pragma unroll
            for (int j = 0; j < 4; j++) acc[mt][nt][j] = 0.f;

    for (int kk = 0; kk < K; kk += 32) {
        // A fill: 128 rows x 32 halves = 512 uint4 slots (raw fp16 bits)
        #pragma unroll
        for (int s = t; s < 512; s += 256) {
            int row = s >> 2;
            int k8 = (s & 3) << 3;          // half offset within k-step
            int r = rowBase + row;
            uint4 u = make_uint4(0, 0, 0, 0);
            if (r < M) u = *(const uint4*)(A + (size_t)r * K + kk + k8);
            int k2 = k8 >> 1;
            As2[k2 + 0][row] = u.x;
            As2[k2 + 1][row] = u.y;
            As2[k2 + 2][row] = u.z;
            As2[k2 + 3][row] = u.w;
        }
        // B fill: pair fp32 rows (2k2, 2k2+1), round to half2
        #pragma unroll
        for (int s = t; s < 512; s += 256) {
            int k2 = s >> 5;
            int n4 = (s & 31) << 2;
            const float* B0 = B + (size_t)(kk + 2 * k2) * 256 + colBase + n4;
            float4 v0 = *(const float4*)B0;
            float4 v1 = *(const float4*)(B0 + 256);
            uint4 w;
            w.x = pack2h(v0.x, v1.x);
            w.y = pack2h(v0.y, v1.y);
            w.z = pack2h(v0.z, v1.z);
            w.w = pack2h(v0.w, v1.w);
            *(uint4*)&Bs2[k2][n4] = w;
        }
        __syncthreads();

        #pragma unroll
        for (int s = 0; s < 2; s++) {
            int kc2 = s * 8;
            uint32_t af[4][4], bf[4][2];
            #pragma unroll
            for (int nt = 0; nt < 4; nt++) {
                int nc = warpN + nt * 8 + lr;
                bf[nt][0] = Bs2[kc2 + lc][nc];
                bf[nt][1] = Bs2[kc2 + 4 + lc][nc];
            }
            #pragma unroll
            for (int mt = 0; mt < 4; mt++) {
                int m = warpM + mt * 16 + lr;
                af[mt][0] = As2[kc2 + lc][m];
                af[mt][1] = As2[kc2 + lc][m + 8];
                af[mt][2] = As2[kc2 + 4 + lc][m];
                af[mt][3] = As2[kc2 + 4 + lc][m + 8];
            }
            #pragma unroll
            for (int mt = 0; mt < 4; mt++)
                #pragma unroll
                for (int nt = 0; nt < 4; nt++)
                    mma_f16(acc[mt][nt], af[mt], bf[nt]);
        }
        __syncthreads();
    }

    // epilogue: bias add + half store + fused BN-stat accumulation (fp32)
    float ls[8], ls2[8];
    #pragma unroll
    for (int j = 0; j < 8; j++) { ls[j] = 0.f; ls2[j] = 0.f; }

    #pragma unroll
    for (int nt = 0; nt < 4; nt++) {
        int col = colBase + warpN + nt * 8 + 2 * lc;
        float b0 = bias[col], b1 = bias[col + 1];
        #pragma unroll
        for (int mt = 0; mt < 4; mt++) {
            int r0 = rowBase + warpM + mt * 16 + lr;
            if (r0 < M) {
                float o0 = acc[mt][nt][0] + b0, o1 = acc[mt][nt][1] + b1;
                *(__half2*)(C + (size_t)r0 * 256 + col) = __floats2half2_rn(o0, o1);
                ls[nt * 2]     += o0;  ls2[nt * 2]     = fmaf(o0, o0, ls2[nt * 2]);
                ls[nt * 2 + 1] += o1;  ls2[nt * 2 + 1] = fmaf(o1, o1, ls2[nt * 2 + 1]);
            }
            int r1 = r0 + 8;
            if (r1 < M) {
                float o2 = acc[mt][nt][2] + b0, o3 = acc[mt][nt][3] + b1;
                *(__half2*)(C + (size_t)r1 * 256 + col) = __floats2half2_rn(o2, o3);
                ls[nt * 2]     += o2;  ls2[nt * 2]     = fmaf(o2, o2, ls2[nt * 2]);
                ls[nt * 2 + 1] += o3;  ls2[nt * 2 + 1] = fmaf(o3, o3, ls2[nt * 2 + 1]);
            }
        }
    }
    __syncthreads();
    #pragma unroll
    for (int nt = 0; nt < 4; nt++) {
        int c0 = warpN + nt * 8 + 2 * lc;
        atomicAdd(&s_s[c0],      ls[nt * 2]);
        atomicAdd(&s_s2[c0],     ls2[nt * 2]);
        atomicAdd(&s_s[c0 + 1],  ls[nt * 2 + 1]);
        atomicAdd(&s_s2[c0 + 1], ls2[nt * 2 + 1]);
    }
    __syncthreads();
    if (t < 128) {
        atomicAdd(&g_sumf[colBase + t],  s_s[t]);
        atomicAdd(&g_sum2f[colBase + t], s_s2[t]);
    }
}

// ---------------- fp16 TC GEMM40: g_p3[M,40] = dinv*(f2(g_mh) @ W3) -------------
// Block: 128 rows, 8 warps (warp = 16 rows x 40 cols = 5 n-tiles of m16n8k16).
__global__ __launch_bounds__(256) void k_gemm40_tc(
    const float* __restrict__ W, int M) {
    const __half* __restrict__ A = g_mh;
    __shared__ uint32_t Bs2[128][OUTD];   // [k2 0..127][n 0..39]  half2 {W[2k2],W[2k2+1]}
    __shared__ uint32_t As2[16][TPAD];    // [k2 within 32-k step][m]
    __shared__ float ssc[HID], ssh[HID];

    int t = threadIdx.x;
    int warp = t >> 5, lane = t & 31;
    int lr = lane >> 2, lc = lane & 3;
    int rowBase = blockIdx.x * 128;
    int warpM = warp * 16;

    ssc[t] = g_scale[t];
    ssh[t] = g_shift[t];
    // W3 -> smem half2 pairs (once)
    for (int s = t; s < 128 * OUTD; s += 256) {
        int k2 = s / OUTD, nc = s % OUTD;
        float w0 = W[(size_t)(2 * k2) * OUTD + nc];
        float w1 = W[(size_t)(2 * k2 + 1) * OUTD + nc];
        Bs2[k2][nc] = pack2h(w0, w1);
    }
    __syncthreads();

    float acc[5][4];
    #pragma unroll
    for (int nt = 0; nt < 5; nt++)
        #pragma unroll
        for (int j = 0; j < 4; j++) acc[nt][j] = 0.f;

    for (int kk = 0; kk < HID; kk += 32) {
        // A fill with fused BN+ReLU, fp16 repack: 512 uint4 slots
        #pragma unroll
        for (int s = t; s < 512; s += 256) {
            int row = s >> 2;
            int k8 = (s & 3) << 3;
            int r = rowBase + row;
            float f[8] = {0.f, 0.f, 0.f, 0.f, 0.f, 0.f, 0.f, 0.f};
            if (r < M) {
                uint4 u = *(const uint4*)(A + (size_t)r * HID + kk + k8);
                h8f(u, f);
            }
            int c = kk + k8;
            #pragma unroll
            for (int j = 0; j < 8; j++)
                f[j] = fmaxf(fmaf(f[j], ssc[c + j], ssh[c + j]), 0.f);
            int k2 = k8 >> 1;
            As2[k2 + 0][row] = pack2h(f[0], f[1]);
            As2[k2 + 1][row] = pack2h(f[2], f[3]);
            As2[k2 + 2][row] = pack2h(f[4], f[5]);
            As2[k2 + 3][row] = pack2h(f[6], f[7]);
        }
        __syncthreads();

        int kk2 = kk >> 1;
        #pragma unroll
        for (int s = 0; s < 2; s++) {
            int kc2 = s * 8;
            uint32_t af[4];
            int m = warpM + lr;
            af[0] = As2[kc2 + lc][m];
            af[1] = As2[kc2 + lc][m + 8];
            af[2] = As2[kc2 + 4 + lc][m];
            af[3] = As2[kc2 + 4 + lc][m + 8];
            #pragma unroll
            for (int nt = 0; nt < 5; nt++) {
                int nc = nt * 8 + lr;
                uint32_t bf[2];
                bf[0] = Bs2[kk2 + kc2 + lc][nc];
                bf[1] = Bs2[kk2 + kc2 + 4 + lc][nc];
                mma_f16(acc[nt], af, bf);
            }
        }
        __syncthreads();
    }

    // epilogue: dinv scale, fp32 store
    int r0 = rowBase + warpM + lr;
    int r1 = r0 + 8;
    float d0 = (r0 < M) ? g_dinv[r0] : 0.f;
    float d1 = (r1 < M) ? g_dinv[r1] : 0.f;
    #pragma unroll
    for (int nt = 0; nt < 5; nt++) {
        int col = nt * 8 + 2 * lc;
        if (r0 < M)
            *(float2*)(g_p3 + (size_t)r0 * OUTD + col) =
                make_float2(acc[nt][0] * d0, acc[nt][1] * d0);
        if (r1 < M)
            *(float2*)(g_p3 + (size_t)r1 * OUTD + col) =
                make_float2(acc[nt][2] * d1, acc[nt][3] * d1);
    }
}

// ---------------- BN params from fused stats -----------------------------------
__global__ void k_bnparams(const float* __restrict__ g, const float* __restrict__ be, int n) {
    int t = threadIdx.x;  // 256
    float s = g_sumf[t], s2 = g_sum2f[t];
    g_sumf[t] = 0.f;
    g_sum2f[t] = 0.f;
    float inv_n = 1.f / (float)n;
    float mean = s * inv_n;
    float var  = fmaf(s2, inv_n, -mean * mean);
    float rs = rsqrtf(var + 1e-5f);
    float sc = rs * g[t];
    g_scale[t] = sc;
    g_shift[t] = be[t] - mean * sc;
}

// ---------------- final: out = log_softmax(g_h3 @ Wl + bl) ---------------------
__global__ void k_final(const float* __restrict__ Wl, const float* __restrict__ bl,
                        float* __restrict__ out, int n) {
    __shared__ float sW[OUTD * OUTD];
    __shared__ float sb[OUTD];
    int tid = threadIdx.x;  // 256
    for (int i = tid; i < OUTD * OUTD; i += 256) sW[i] = Wl[i];
    if (tid < OUTD) sb[tid] = bl[tid];
    __syncthreads();
    int warp = tid >> 5, lane = tid & 31;
    int row = blockIdx.x * 8 + warp;
    if (row >= n) return;
    const float* a = g_h3 + (size_t)row * OUTD;
    float a_lo = a[lane];
    float a_hi = (lane < 8) ? a[32 + lane] : 0.f;
    float z0 = sb[lane];
    float z1 = (lane < 8) ? sb[32 + lane] : -1e30f;
    #pragma unroll
    for (int k = 0; k < OUTD; k++) {
        float ak = (k < 32) ? __shfl_sync(0xFFFFFFFFu, a_lo, k)
                            : __shfl_sync(0xFFFFFFFFu, a_hi, k - 32);
        z0 = fmaf(ak, sW[k * OUTD + lane], z0);
        if (lane < 8) z1 = fmaf(ak, sW[k * OUTD + 32 + lane], z1);
    }
    float mx = fmaxf(z0, z1);
    #pragma unroll
    for (int o = 16; o; o >>= 1) mx = fmaxf(mx, __shfl_xor_sync(0xFFFFFFFFu, mx, o));
    float es = expf(z0 - mx) + ((lane < 8) ? expf(z1 - mx) : 0.f);
    #pragma unroll
    for (int o = 16; o; o >>= 1) es += __shfl_xor_sync(0xFFFFFFFFu, es, o);
    float L = mx + logf(es);
    out[(size_t)row * OUTD + lane] = z0 - L;
    if (lane < 8) out[(size_t)row * OUTD + 32 + lane] = z1 - L;
}

// ---------------- launch (kernel launches ONLY — no CUDA API calls) ------------
extern "C" void kernel_launch(void* const* d_in, const int* in_sizes, int n_in,
                              void* d_out, int out_size) {
    const float* x   = (const float*)d_in[0];
    const int*   ei  = (const int*)d_in[1];      // int32 edge_index (JAX default)
    const float* W1  = (const float*)d_in[2];
    const float* b1  = (const float*)d_in[3];
    const float* g1  = (const float*)d_in[4];
    const float* be1 = (const float*)d_in[5];
    const float* W2  = (const float*)d_in[6];
    const float* b2  = (const float*)d_in[7];
    const float* g2  = (const float*)d_in[8];
    const float* be2 = (const float*)d_in[9];
    const float* W3  = (const float*)d_in[10];
    const float* b3  = (const float*)d_in[11];
    const float* Wl  = (const float*)d_in[12];
    const float* bl  = (const float*)d_in[13];
    float* out = (float*)d_out;

    int n = in_sizes[0] / INF;     // 50000
    int e = in_sizes[1] / 2;       // 800000
    int nb = (n + 1023) / 1024;    // scan blocks (49)

    k_deg<<<(e + 255) / 256, 256>>>(ei, e, n);
    k_scan1<<<nb, 1024>>>(n);
    k_scan23<<<nb, 1024>>>(n, nb);
    k_scatter<<<(e + 255) / 256, 256>>>(ei, e, n);
    int total8 = n * INF / 8;
    k_xtoh<<<(total8 + 255) / 256, 256>>>(x, total8);

    // layer 1: aggregate-first (width 128 fp16), then fp16 TC GEMM (stats fused)
    k_aggX<<<n, 32>>>();
    dim3 gg((n + 127) / 128, 2);
    k_gemm256_tc<1><<<gg, 256>>>(W1, b1, n);
    k_bnparams<<<1, 256>>>(g1, be1, n);

    // layer 2: aggregate f1(m1) (width 256 fp16), then fp16 TC GEMM (stats fused)
    k_agg256<<<n, 32>>>();
    k_gemm256_tc<2><<<gg, 256>>>(W2, b2, n);
    k_bnparams<<<1, 256>>>(g2, be2, n);

    // layer 3: fp16 TC GEMM (f2 fused into A-fill, dinv in epilogue), agg width 40
    k_gemm40_tc<<<(n + 127) / 128, 256>>>(W3, n);
    k_agg40<<<(n + 7) / 8, 256>>>(b3, n);

    // final linear + log_softmax
    k_final<<<(n + 7) / 8, 256>>>(Wl, bl, out, n);
}

// round 14
// speedup vs baseline: 2.3347x; 1.1037x over previous
#include <cuda_runtime.h>
#include <cuda_fp16.h>
#include <math.h>
#include <stdint.h>

#define NN 50000
#define EE 800000
#define INF 128
#define HID 256
#define OUTD 40

// ---------------- scratch (static device globals; no allocation) -------------
__device__ int    g_deg[NN];        // indeg (self-loop added analytically)
__device__ float  g_dinv[NN];
__device__ int    g_rowptr[NN + 1];
__device__ int    g_cursor[NN];
__device__ int    g_col[EE];
__device__ int    g_bsum[64];
__device__ __align__(16) __half g_xh[(size_t)NN * INF];    // x in fp16
__device__ __align__(16) __half g_aggxh[(size_t)NN * INF]; // Â x (fp16)
__device__ __align__(16) __half g_mh[(size_t)NN * HID];    // conv outputs m1/m2 (fp16)
__device__ __align__(16) __half g_aggh[(size_t)NN * HID];  // Â f1(m1) (fp16)
__device__ __align__(16) __half g_p3h[(size_t)NN * OUTD];  // dinv*(f2(m2)@W3) fp16
__device__ __align__(16) uint32_t g_w1h[64 * 256];         // W1 k-pair fp16
__device__ __align__(16) uint32_t g_w2h[128 * 256];        // W2 k-pair fp16
__device__ __align__(16) uint32_t g_w3h[128 * OUTD];       // W3 k-pair fp16
__device__ float  g_sumf[HID];     // fused BN stats (fp32, atomic)
__device__ float  g_sum2f[HID];
__device__ float  g_scale[HID];
__device__ float  g_shift[HID];

// ---------------- half pack/unpack helpers -------------------------------------
__device__ __forceinline__ void h4f(uint2 u, float f[4]) {
    float2 p0 = __half22float2(*(__half2*)&u.x);
    float2 p1 = __half22float2(*(__half2*)&u.y);
    f[0] = p0.x; f[1] = p0.y; f[2] = p1.x; f[3] = p1.y;
}
__device__ __forceinline__ uint2 f4h(const float f[4]) {
    __half2 h0 = __floats2half2_rn(f[0], f[1]);
    __half2 h1 = __floats2half2_rn(f[2], f[3]);
    uint2 u;
    u.x = *(uint32_t*)&h0;
    u.y = *(uint32_t*)&h1;
    return u;
}
__device__ __forceinline__ void h8f(uint4 u, float f[8]) {
    h4f(make_uint2(u.x, u.y), f);
    h4f(make_uint2(u.z, u.w), f + 4);
}
__device__ __forceinline__ uint4 f8h(const float f[8]) {
    uint2 a = f4h(f), b = f4h(f + 4);
    return make_uint4(a.x, a.y, b.x, b.y);
}
__device__ __forceinline__ uint32_t pack2h(float a, float b) {
    __half2 h = __floats2half2_rn(a, b);
    return *(uint32_t*)&h;
}
__device__ __forceinline__ void cp16(void* smem, const void* g) {
    uint32_t sa = (uint32_t)__cvta_generic_to_shared(smem);
    asm volatile("cp.async.cg.shared.global [%0], [%1], 16;" :: "r"(sa), "l"(g));
}

// ---------------- graph preprocessing ----------------------------------------
__global__ void k_deg(const int* __restrict__ ei, int e, int n) {
    int i = blockIdx.x * blockDim.x + threadIdx.x;
    if (i < e) {
        int d = ei[e + i];
        if ((unsigned)d < (unsigned)n) atomicAdd(&g_deg[d], 1);
    }
}

__global__ __launch_bounds__(1024) void k_scan1(int n) {
    __shared__ int warpsums[32];
    int b = blockIdx.x, tid = threadIdx.x;
    int i = b * 1024 + tid;
    int v = 0;
    if (i < n) {
        int d = g_deg[i];
        v = d;
        g_dinv[i] = rsqrtf((float)(d + 1));
    }
    int x = v;
    #pragma unroll
    for (int o = 1; o < 32; o <<= 1) {
        int y = __shfl_up_sync(0xFFFFFFFFu, x, o);
        if ((tid & 31) >= o) x += y;
    }
    if ((tid & 31) == 31) warpsums[tid >> 5] = x;
    __syncthreads();
    if (tid < 32) {
        int w = warpsums[tid];
        #pragma unroll
        for (int o = 1; o < 32; o <<= 1) {
            int y = __shfl_up_sync(0xFFFFFFFFu, w, o);
            if (tid >= o) w += y;
        }
        warpsums[tid] = w;
    }
    __syncthreads();
    int incl = x + ((tid >= 32) ? warpsums[(tid >> 5) - 1] : 0);
    if (i < n) g_rowptr[i + 1] = incl;
    if (tid == 1023) g_bsum[b] = incl;
}

__global__ __launch_bounds__(1024) void k_scan23(int n, int nb) {
    __shared__ int w0s;
    __shared__ int s_off;
    int tid = threadIdx.x;
    int v = 0, x = 0;
    if (tid < 64) {
        v = (tid < nb) ? g_bsum[tid] : 0;
        x = v;
        #pragma unroll
        for (int o = 1; o < 32; o <<= 1) {
            int y = __shfl_up_sync(0xFFFFFFFFu, x, o);
            if ((tid & 31) >= o) x += y;
        }
        if (tid == 31) w0s = x;
    }
    __syncthreads();
    if (tid < 64) {
        int incl = x + ((tid >= 32) ? w0s : 0);
        if (tid == blockIdx.x) s_off = incl - v;
    }
    __syncthreads();
    int i = blockIdx.x * 1024 + tid;
    if (i < n) {
        int indeg = g_deg[i];
        int val = g_rowptr[i + 1] + s_off;
        g_rowptr[i + 1] = val;
        g_cursor[i] = val - indeg;
        g_deg[i] = 0;                               // reset for next replay
    }
    if (i == 0) g_rowptr[0] = 0;
}

__global__ void k_scatter(const int* __restrict__ ei, int e, int n) {
    int i = blockIdx.x * blockDim.x + threadIdx.x;
    if (i < e) {
        int s = ei[i], d = ei[e + i];
        if ((unsigned)d < (unsigned)n) {
            s = min(max(s, 0), n - 1);
            int pos = atomicAdd(&g_cursor[d], 1);
            g_col[pos] = s;
        }
    }
}

// ---------------- conversions ----------------------------------------------------
__global__ void k_xtoh(const float* __restrict__ x, int total8) {
    int i = blockIdx.x * blockDim.x + threadIdx.x;
    if (i < total8) {
        float4 a = ((const float4*)x)[i * 2];
        float4 b = ((const float4*)x)[i * 2 + 1];
        float f[8] = {a.x, a.y, a.z, a.w, b.x, b.y, b.z, b.w};
        ((uint4*)g_xh)[i] = f8h(f);
    }
}

// weights -> fp16 k-pair interleaved: g_w*[k2][n] = {W[2k2][n], W[2k2+1][n]}
__global__ void k_wconv(const float* __restrict__ W1, const float* __restrict__ W2,
                        const float* __restrict__ W3) {
    int i = blockIdx.x * blockDim.x + threadIdx.x;
    if (i < 64 * 256) {
        int k2 = i >> 8, nc = i & 255;
        g_w1h[i] = pack2h(W1[(size_t)(2 * k2) * 256 + nc], W1[(size_t)(2 * k2 + 1) * 256 + nc]);
        return;
    }
    int j = i - 64 * 256;
    if (j < 128 * 256) {
        int k2 = j >> 8, nc = j & 255;
        g_w2h[j] = pack2h(W2[(size_t)(2 * k2) * 256 + nc], W2[(size_t)(2 * k2 + 1) * 256 + nc]);
        return;
    }
    int m = j - 128 * 256;
    if (m < 128 * OUTD) {
        int k2 = m / OUTD, nc = m % OUTD;
        g_w3h[m] = pack2h(W3[(size_t)(2 * k2) * OUTD + nc], W3[(size_t)(2 * k2 + 1) * OUTD + nc]);
    }
}

// ---------------- aggregation kernels (fp16 gather) -----------------------------
__global__ void k_aggX() {
    int i = blockIdx.x, t = threadIdx.x;  // 32 threads, 4 halves each (128)
    const uint2* __restrict__ x2 = (const uint2*)g_xh;
    float di = g_dinv[i];
    float acc[4], f[4];
    h4f(x2[(size_t)i * 32 + t], f);
    #pragma unroll
    for (int j = 0; j < 4; j++) acc[j] = di * f[j];
    int e0 = g_rowptr[i], e1 = g_rowptr[i + 1];
    int e = e0;
    for (; e + 1 < e1; e += 2) {
        int s0 = g_col[e], s1 = g_col[e + 1];
        float d0 = g_dinv[s0], d1 = g_dinv[s1];
        float f0[4], f1[4];
        h4f(x2[(size_t)s0 * 32 + t], f0);
        h4f(x2[(size_t)s1 * 32 + t], f1);
        #pragma unroll
        for (int j = 0; j < 4; j++) acc[j] += d0 * f0[j] + d1 * f1[j];
    }
    if (e < e1) {
        int s = g_col[e];
        float d = g_dinv[s];
        h4f(x2[(size_t)s * 32 + t], f);
        #pragma unroll
        for (int j = 0; j < 4; j++) acc[j] += d * f[j];
    }
    #pragma unroll
    for (int j = 0; j < 4; j++) acc[j] *= di;
    ((uint2*)g_aggxh)[(size_t)i * 32 + t] = f4h(acc);
}

__global__ void k_agg256() {
    int i = blockIdx.x, t = threadIdx.x;  // 32 threads, 8 halves each (256)
    const uint4* __restrict__ m4 = (const uint4*)g_mh;
    float sc[8], sh[8];
    {
        float4 s0 = ((const float4*)g_scale)[2 * t];
        float4 s1 = ((const float4*)g_scale)[2 * t + 1];
        float4 h0 = ((const float4*)g_shift)[2 * t];
        float4 h1 = ((const float4*)g_shift)[2 * t + 1];
        sc[0]=s0.x; sc[1]=s0.y; sc[2]=s0.z; sc[3]=s0.w;
        sc[4]=s1.x; sc[5]=s1.y; sc[6]=s1.z; sc[7]=s1.w;
        sh[0]=h0.x; sh[1]=h0.y; sh[2]=h0.z; sh[3]=h0.w;
        sh[4]=h1.x; sh[5]=h1.y; sh[6]=h1.z; sh[7]=h1.w;
    }
    float di = g_dinv[i];
    float acc[8], f[8];
    h8f(m4[(size_t)i * 32 + t], f);
    #pragma unroll
    for (int j = 0; j < 8; j++)
        acc[j] = di * fmaxf(fmaf(f[j], sc[j], sh[j]), 0.f);
    int e0 = g_rowptr[i], e1 = g_rowptr[i + 1];
    int e = e0;
    for (; e + 1 < e1; e += 2) {
        int s0 = g_col[e], s1 = g_col[e + 1];
        float d0 = g_dinv[s0], d1 = g_dinv[s1];
        float f0[8], f1[8];
        h8f(m4[(size_t)s0 * 32 + t], f0);
        h8f(m4[(size_t)s1 * 32 + t], f1);
        #pragma unroll
        for (int j = 0; j < 8; j++)
            acc[j] += d0 * fmaxf(fmaf(f0[j], sc[j], sh[j]), 0.f)
                    + d1 * fmaxf(fmaf(f1[j], sc[j], sh[j]), 0.f);
    }
    if (e < e1) {
        int s = g_col[e];
        float d = g_dinv[s];
        h8f(m4[(size_t)s * 32 + t], f);
        #pragma unroll
        for (int j = 0; j < 8; j++)
            acc[j] += d * fmaxf(fmaf(f[j], sc[j], sh[j]), 0.f);
    }
    #pragma unroll
    for (int j = 0; j < 8; j++) acc[j] *= di;
    ((uint4*)g_aggh)[(size_t)i * 32 + t] = f8h(acc);
}

// ---------------- fp16 m16n8k16 MMA helper --------------------------------------
__device__ __forceinline__ void mma_f16(float c[4], const uint32_t a[4], const uint32_t b[2]) {
    asm volatile(
        "mma.sync.aligned.m16n8k16.row.col.f32.f16.f16.f32 "
        "{%0,%1,%2,%3}, {%4,%5,%6,%7}, {%8,%9}, {%0,%1,%2,%3};"
        : "+f"(c[0]), "+f"(c[1]), "+f"(c[2]), "+f"(c[3])
        : "r"(a[0]), "r"(a[1]), "r"(a[2]), "r"(a[3]), "r"(b[0]), "r"(b[1]));
}

#define TPAD 136    // B word stride: 136 % 32 == 8 -> conflict-free
#define ASTRIDE 20  // A word stride: {k*20 mod 32} covers all banks

// ---------------- fp16 TC GEMM (cp.async double-buffered) -----------------------
// C_h[M,256] = A_h[M,K] @ Wh[K,256] + bias ; BN stats fused.
template <int LAYER>
__global__ __launch_bounds__(256) void k_gemm256_tc(
    const float* __restrict__ bias, int M) {
    constexpr int K = (LAYER == 1) ? INF : HID;
    constexpr int NSTEP = K / 32;
    const __half* __restrict__ A = (LAYER == 1) ? g_aggxh : g_aggh;
    const uint32_t* __restrict__ Bw = (LAYER == 1) ? g_w1h : g_w2h;  // [K/2][256]
    __half* __restrict__ C = g_mh;

    __shared__ uint32_t As[2][128][ASTRIDE];  // [stage][m][k2] (16 of 20 used)
    __shared__ uint32_t Bs[2][16][TPAD];      // [stage][k2][n]
    __shared__ float s_s[128], s_s2[128];

    int t = threadIdx.x;
    int warp = t >> 5, lane = t & 31;
    int lr = lane >> 2, lc = lane & 3;
    int warpM = (warp >> 2) * 64;
    int warpN = (warp & 3) * 32;
    int rowBase = blockIdx.x * 128;
    int colBase = blockIdx.y * 128;

    if (t < 128) { s_s[t] = 0.f; s_s2[t] = 0.f; }

    float acc[4][4][4];
    #pragma unroll
    for (int mt = 0; mt < 4; mt++)
        #pragma unroll
        for (int nt = 0; nt < 4; nt++)
            #pragma unroll
            for (int j = 0; j < 4; j++) acc[mt][nt][j] = 0.f;

    auto load_stage = [&](int st, int kk) {
        #pragma unroll
        for (int h = 0; h < 2; h++) {
            int s = t + h * 256;
            int row = s >> 2;
            int c4 = (s & 3) << 2;                 // uint32 offset in row
            int r = min(rowBase + row, M - 1);     // clamp: dup rows, results unused
            cp16(&As[st][row][c4], A + (size_t)r * K + kk + (c4 << 1));
        }
        int kk2 = kk >> 1;
        #pragma unroll
        for (int h = 0; h < 2; h++) {
            int s = t + h * 256;
            int k2 = s >> 5;
            int n4 = (s & 31) << 2;
            cp16(&Bs[st][k2][n4], Bw + (size_t)(kk2 + k2) * 256 + colBase + n4);
        }
        asm volatile("cp.async.commit_group;");
    };

    load_stage(0, 0);
    #pragma unroll
    for (int i = 0; i < NSTEP; i++) {
        if (i + 1 < NSTEP) {
            load_stage((i + 1) & 1, (i + 1) * 32);
            asm volatile("cp.async.wait_group 1;");
        } else {
            asm volatile("cp.async.wait_group 0;");
        }
        __syncthreads();
        int st = i & 1;
        #pragma unroll
        for (int s = 0; s < 2; s++) {
            int kc2 = s * 8;
            uint32_t af[4][4], bf[4][2];
            #pragma unroll
            for (int nt = 0; nt < 4; nt++) {
                int nc = warpN + nt * 8 + lr;
                bf[nt][0] = Bs[st][kc2 + lc][nc];
                bf[nt][1] = Bs[st][kc2 + 4 + lc][nc];
            }
            #pragma unroll
            for (int mt = 0; mt < 4; mt++) {
                int m = warpM + mt * 16 + lr;
                af[mt][0] = As[st][m][kc2 + lc];
                af[mt][1] = As[st][m + 8][kc2 + lc];
                af[mt][2] = As[st][m][kc2 + 4 + lc];
                af[mt][3] = As[st][m + 8][kc2 + 4 + lc];
            }
            #pragma unroll
            for (int mt = 0; mt < 4; mt++)
                #pragma unroll
                for (int nt = 0; nt < 4; nt++)
                    mma_f16(acc[mt][nt], af[mt], bf[nt]);
        }
        __syncthreads();
    }

    // epilogue: bias add + half store + fused BN-stat accumulation (fp32)
    float ls[8], ls2[8];
    #pragma unroll
    for (int j = 0; j < 8; j++) { ls[j] = 0.f; ls2[j] = 0.f; }

    #pragma unroll
    for (int nt = 0; nt < 4; nt++) {
        int col = colBase + warpN + nt * 8 + 2 * lc;
        float b0 = bias[col], b1 = bias[col + 1];
        #pragma unroll
        for (int mt = 0; mt < 4; mt++) {
            int r0 = rowBase + warpM + mt * 16 + lr;
            if (r0 < M) {
                float o0 = acc[mt][nt][0] + b0, o1 = acc[mt][nt][1] + b1;
                *(__half2*)(C + (size_t)r0 * 256 + col) = __floats2half2_rn(o0, o1);
                ls[nt * 2]     += o0;  ls2[nt * 2]     = fmaf(o0, o0, ls2[nt * 2]);
                ls[nt * 2 + 1] += o1;  ls2[nt * 2 + 1] = fmaf(o1, o1, ls2[nt * 2 + 1]);
            }
            int r1 = r0 + 8;
            if (r1 < M) {
                float o2 = acc[mt][nt][2] + b0, o3 = acc[mt][nt][3] + b1;
                *(__half2*)(C + (size_t)r1 * 256 + col) = __floats2half2_rn(o2, o3);
                ls[nt * 2]     += o2;  ls2[nt * 2]     = fmaf(o2, o2, ls2[nt * 2]);
                ls[nt * 2 + 1] += o3;  ls2[nt * 2 + 1] = fmaf(o3, o3, ls2[nt * 2 + 1]);
            }
        }
    }
    __syncthreads();
    #pragma unroll
    for (int nt = 0; nt < 4; nt++) {
        int c0 = warpN + nt * 8 + 2 * lc;
        atomicAdd(&s_s[c0],      ls[nt * 2]);
        atomicAdd(&s_s2[c0],     ls2[nt * 2]);
        atomicAdd(&s_s[c0 + 1],  ls[nt * 2 + 1]);
        atomicAdd(&s_s2[c0 + 1], ls2[nt * 2 + 1]);
    }
    __syncthreads();
    if (t < 128) {
        atomicAdd(&g_sumf[colBase + t],  s_s[t]);
        atomicAdd(&g_sum2f[colBase + t], s_s2[t]);
    }
}

// ---------------- fp16 TC GEMM40: g_p3h[M,40] = dinv*(f2(g_mh) @ W3) ------------
__global__ __launch_bounds__(256) void k_gemm40_tc(int M) {
    const __half* __restrict__ A = g_mh;
    __shared__ uint32_t Bs2[128][OUTD];   // [k2][n] half2 {W[2k2],W[2k2+1]}
    __shared__ uint32_t As2[16][TPAD];    // [k2 within 32-k step][m]
    __shared__ float ssc[HID], ssh[HID];

    int t = threadIdx.x;
    int warp = t >> 5, lane = t & 31;
    int lr = lane >> 2, lc = lane & 3;
    int rowBase = blockIdx.x * 128;
    int warpM = warp * 16;

    ssc[t] = g_scale[t];
    ssh[t] = g_shift[t];
    for (int s = t; s < 128 * OUTD; s += 256)
        ((uint32_t*)Bs2)[ (s / OUTD) * OUTD + (s % OUTD) ] = g_w3h[s];
    __syncthreads();

    float acc[5][4];
    #pragma unroll
    for (int nt = 0; nt < 5; nt++)
        #pragma unroll
        for (int j = 0; j < 4; j++) acc[nt][j] = 0.f;

    for (int kk = 0; kk < HID; kk += 32) {
        // A fill with fused BN+ReLU, fp16 repack
        #pragma unroll
        for (int s = t; s < 512; s += 256) {
            int row = s >> 2;
            int k8 = (s & 3) << 3;
            int r = rowBase + row;
            float f[8] = {0.f, 0.f, 0.f, 0.f, 0.f, 0.f, 0.f, 0.f};
            if (r < M) {
                uint4 u = *(const uint4*)(A + (size_t)r * HID + kk + k8);
                h8f(u, f);
            }
            int c = kk + k8;
            #pragma unroll
            for (int j = 0; j < 8; j++)
                f[j] = fmaxf(fmaf(f[j], ssc[c + j], ssh[c + j]), 0.f);
            int k2 = k8 >> 1;
            As2[k2 + 0][row] = pack2h(f[0], f[1]);
            As2[k2 + 1][row] = pack2h(f[2], f[3]);
            As2[k2 + 2][row] = pack2h(f[4], f[5]);
            As2[k2 + 3][row] = pack2h(f[6], f[7]);
        }
        __syncthreads();

        int kk2 = kk >> 1;
        #pragma unroll
        for (int s = 0; s < 2; s++) {
            int kc2 = s * 8;
            uint32_t af[4];
            int m = warpM + lr;
            af[0] = As2[kc2 + lc][m];
            af[1] = As2[kc2 + lc][m + 8];
            af[2] = As2[kc2 + 4 + lc][m];
            af[3] = As2[kc2 + 4 + lc][m + 8];
            #pragma unroll
            for (int nt = 0; nt < 5; nt++) {
                int nc = nt * 8 + lr;
                uint32_t bf[2];
                bf[0] = Bs2[kk2 + kc2 + lc][nc];
                bf[1] = Bs2[kk2 + kc2 + 4 + lc][nc];
                mma_f16(acc[nt], af, bf);
            }
        }
        __syncthreads();
    }

    // epilogue: dinv scale, fp16 store
    int r0 = rowBase + warpM + lr;
    int r1 = r0 + 8;
    float d0 = (r0 < M) ? g_dinv[r0] : 0.f;
    float d1 = (r1 < M) ? g_dinv[r1] : 0.f;
    #pragma unroll
    for (int nt = 0; nt < 5; nt++) {
        int col = nt * 8 + 2 * lc;
        if (r0 < M)
            *(uint32_t*)(g_p3h + (size_t)r0 * OUTD + col) =
                pack2h(acc[nt][0] * d0, acc[nt][1] * d0);
        if (r1 < M)
            *(uint32_t*)(g_p3h + (size_t)r1 * OUTD + col) =
                pack2h(acc[nt][2] * d1, acc[nt][3] * d1);
    }
}

// ---------------- BN params from fused stats -----------------------------------
__global__ void k_bnparams(const float* __restrict__ g, const float* __restrict__ be, int n) {
    int t = threadIdx.x;  // 256
    float s = g_sumf[t], s2 = g_sum2f[t];
    g_sumf[t] = 0.f;
    g_sum2f[t] = 0.f;
    float inv_n = 1.f / (float)n;
    float mean = s * inv_n;
    float var  = fmaf(s2, inv_n, -mean * mean);
    float rs = rsqrtf(var + 1e-5f);
    float sc = rs * g[t];
    g_scale[t] = sc;
    g_shift[t] = be[t] - mean * sc;
}

// ---------------- fused: gather p3h + b3, then log_softmax(h3 @ Wl + bl) --------
__global__ void k_final40(const float* __restrict__ Wl, const float* __restrict__ bl,
                          const float* __restrict__ b3, float* __restrict__ out, int n) {
    __shared__ float sW[OUTD * OUTD];
    __shared__ float sb[OUTD], sb3[OUTD];
    int tid = threadIdx.x;  // 256
    for (int i = tid; i < OUTD * OUTD; i += 256) sW[i] = Wl[i];
    if (tid < OUTD) { sb[tid] = bl[tid]; sb3[tid] = b3[tid]; }
    __syncthreads();
    int warp = tid >> 5, lane = tid & 31;
    int node = blockIdx.x * 8 + warp;
    if (node >= n) return;

    // gather h3[node] (lanes 0..9 hold 4 values each)
    float a[4] = {0.f, 0.f, 0.f, 0.f};
    if (lane < 10) {
        const uint2* p2 = (const uint2*)g_p3h;   // 10 uint2 per row
        uint2 u = p2[(size_t)node * 10 + lane];
        h4f(u, a);
        int e0 = g_rowptr[node], e1 = g_rowptr[node + 1];
        for (int e = e0; e < e1; e++) {
            float f[4];
            h4f(p2[(size_t)g_col[e] * 10 + lane], f);
            a[0] += f[0]; a[1] += f[1]; a[2] += f[2]; a[3] += f[3];
        }
        float di = g_dinv[node];
        #pragma unroll
        for (int j = 0; j < 4; j++) a[j] = a[j] * di + sb3[lane * 4 + j];
    }

    // z = h3 @ Wl + bl (h3 redistributed via shfl)
    float z0 = sb[lane];
    float z1 = (lane < 8) ? sb[32 + lane] : -1e30f;
    #pragma unroll
    for (int k = 0; k < OUTD; k++) {
        float hk = __shfl_sync(0xFFFFFFFFu, a[k & 3], k >> 2);
        z0 = fmaf(hk, sW[k * OUTD + lane], z0);
        if (lane < 8) z1 = fmaf(hk, sW[k * OUTD + 32 + lane], z1);
    }
    float mx = fmaxf(z0, z1);
    #pragma unroll
    for (int o = 16; o; o >>= 1) mx = fmaxf(mx, __shfl_xor_sync(0xFFFFFFFFu, mx, o));
    float es = expf(z0 - mx) + ((lane < 8) ? expf(z1 - mx) : 0.f);
    #pragma unroll
    for (int o = 16; o; o >>= 1) es += __shfl_xor_sync(0xFFFFFFFFu, es, o);
    float L = mx + logf(es);
    out[(size_t)node * OUTD + lane] = z0 - L;
    if (lane < 8) out[(size_t)node * OUTD + 32 + lane] = z1 - L;
}

// ---------------- launch (kernel launches ONLY — no CUDA API calls) ------------
extern "C" void kernel_launch(void* const* d_in, const int* in_sizes, int n_in,
                              void* d_out, int out_size) {
    const float* x   = (const float*)d_in[0];
    const int*   ei  = (const int*)d_in[1];      // int32 edge_index (JAX default)
    const float* W1  = (const float*)d_in[2];
    const float* b1  = (const float*)d_in[3];
    const float* g1  = (const float*)d_in[4];
    const float* be1 = (const float*)d_in[5];
    const float* W2  = (const float*)d_in[6];
    const float* b2  = (const float*)d_in[7];
    const float* g2  = (const float*)d_in[8];
    const float* be2 = (const float*)d_in[9];
    const float* W3  = (const float*)d_in[10];
    const float* b3  = (const float*)d_in[11];
    const float* Wl  = (const float*)d_in[12];
    const float* bl  = (const float*)d_in[13];
    float* out = (float*)d_out;

    int n = in_sizes[0] / INF;     // 50000
    int e = in_sizes[1] / 2;       // 800000
    int nb = (n + 1023) / 1024;    // scan blocks (49)

    k_wconv<<<(64 * 256 + 128 * 256 + 128 * OUTD + 255) / 256, 256>>>(W1, W2, W3);
    k_deg<<<(e + 255) / 256, 256>>>(ei, e, n);
    k_scan1<<<nb, 1024>>>(n);
    k_scan23<<<nb, 1024>>>(n, nb);
    k_scatter<<<(e + 255) / 256, 256>>>(ei, e, n);
    int total8 = n * INF / 8;
    k_xtoh<<<(total8 + 255) / 256, 256>>>(x, total8);

    // layer 1: aggregate-first (width 128 fp16), then pipelined fp16 TC GEMM
    k_aggX<<<n, 32>>>();
    dim3 gg((n + 127) / 128, 2);
    k_gemm256_tc<1><<<gg, 256>>>(b1, n);
    k_bnparams<<<1, 256>>>(g1, be1, n);

    // layer 2: aggregate f1(m1) (width 256 fp16), then pipelined fp16 TC GEMM
    k_agg256<<<n, 32>>>();
    k_gemm256_tc<2><<<gg, 256>>>(b2, n);
    k_bnparams<<<1, 256>>>(g2, be2, n);

    // layer 3: fp16 TC GEMM (f2 fused into A-fill, dinv in epilogue)
    k_gemm40_tc<<<(n + 127) / 128, 256>>>(n);

    // fused width-40 aggregation + final linear + log_softmax
    k_final40<<<(n + 7) / 8, 256>>>(Wl, bl, b3, out, n);
}

// round 15
// speedup vs baseline: 2.4164x; 1.0350x over previous
#include <cuda_runtime.h>
#include <cuda_fp16.h>
#include <math.h>
#include <stdint.h>

#define NN 50000
#define EE 800000
#define INF 128
#define HID 256
#define OUTD 40

// ---------------- scratch (static device globals; no allocation) -------------
__device__ int    g_deg[NN];        // indeg (self-loop added analytically)
__device__ float  g_dinv[NN];
__device__ int    g_rowptr[NN + 1];
__device__ int    g_cursor[NN];
__device__ int    g_col[EE];
__device__ int    g_bsum[64];
__device__ __align__(16) __half g_xh[(size_t)NN * INF];    // x in fp16
__device__ __align__(16) __half g_aggxh[(size_t)NN * INF]; // Â x (fp16)
__device__ __align__(16) __half g_mh[(size_t)NN * HID];    // conv outputs m1/m2 (fp16)
__device__ __align__(16) __half g_aggh[(size_t)NN * HID];  // Â f1(m1) (fp16)
__device__ __align__(16) __half g_p3h[(size_t)NN * OUTD];  // dinv*(f2(m2)@W3) fp16
__device__ __align__(16) uint32_t g_w1h[64 * 256];         // W1 k-pair fp16
__device__ __align__(16) uint32_t g_w2h[128 * 256];        // W2 k-pair fp16
__device__ __align__(16) uint32_t g_w3h[128 * OUTD];       // W3 k-pair fp16
__device__ float  g_sumf[HID];     // fused BN stats (fp32, atomic)
__device__ float  g_sum2f[HID];
__device__ float  g_scale[HID];
__device__ float  g_shift[HID];

// ---------------- half pack/unpack helpers -------------------------------------
__device__ __forceinline__ void h4f(uint2 u, float f[4]) {
    float2 p0 = __half22float2(*(__half2*)&u.x);
    float2 p1 = __half22float2(*(__half2*)&u.y);
    f[0] = p0.x; f[1] = p0.y; f[2] = p1.x; f[3] = p1.y;
}
__device__ __forceinline__ uint2 f4h(const float f[4]) {
    __half2 h0 = __floats2half2_rn(f[0], f[1]);
    __half2 h1 = __floats2half2_rn(f[2], f[3]);
    uint2 u;
    u.x = *(uint32_t*)&h0;
    u.y = *(uint32_t*)&h1;
    return u;
}
__device__ __forceinline__ void h8f(uint4 u, float f[8]) {
    h4f(make_uint2(u.x, u.y), f);
    h4f(make_uint2(u.z, u.w), f + 4);
}
__device__ __forceinline__ uint4 f8h(const float f[8]) {
    uint2 a = f4h(f), b = f4h(f + 4);
    return make_uint4(a.x, a.y, b.x, b.y);
}
__device__ __forceinline__ uint32_t pack2h(float a, float b) {
    __half2 h = __floats2half2_rn(a, b);
    return *(uint32_t*)&h;
}
__device__ __forceinline__ void cp16(void* smem, const void* g) {
    uint32_t sa = (uint32_t)__cvta_generic_to_shared(smem);
    asm volatile("cp.async.cg.shared.global [%0], [%1], 16;" :: "r"(sa), "l"(g));
}

// ---------------- merged preprocessing: wconv + xtoh + deg ----------------------
__global__ void k_prep(const int* __restrict__ ei,
                       const float* __restrict__ x,
                       const float* __restrict__ W1,
                       const float* __restrict__ W2,
                       const float* __restrict__ W3,
                       int e, int n, int total8) {
    int i = blockIdx.x * blockDim.x + threadIdx.x;
    // x -> fp16 (8 floats per thread)
    if (i < total8) {
        float4 a = ((const float4*)x)[i * 2];
        float4 b = ((const float4*)x)[i * 2 + 1];
        float f[8] = {a.x, a.y, a.z, a.w, b.x, b.y, b.z, b.w};
        ((uint4*)g_xh)[i] = f8h(f);
    }
    // in-degree count
    if (i < e) {
        int d = ei[e + i];
        if ((unsigned)d < (unsigned)n) atomicAdd(&g_deg[d], 1);
    }
    // weights -> fp16 k-pair interleaved
    if (i < 64 * 256) {
        int k2 = i >> 8, nc = i & 255;
        g_w1h[i] = pack2h(W1[(size_t)(2 * k2) * 256 + nc], W1[(size_t)(2 * k2 + 1) * 256 + nc]);
    }
    if (i < 128 * 256) {
        int k2 = i >> 8, nc = i & 255;
        g_w2h[i] = pack2h(W2[(size_t)(2 * k2) * 256 + nc], W2[(size_t)(2 * k2 + 1) * 256 + nc]);
    }
    if (i < 128 * OUTD) {
        int k2 = i / OUTD, nc = i % OUTD;
        g_w3h[i] = pack2h(W3[(size_t)(2 * k2) * OUTD + nc], W3[(size_t)(2 * k2 + 1) * OUTD + nc]);
    }
}

// ---------------- CSR build -----------------------------------------------------
__global__ __launch_bounds__(1024) void k_scan1(int n) {
    __shared__ int warpsums[32];
    int b = blockIdx.x, tid = threadIdx.x;
    int i = b * 1024 + tid;
    int v = 0;
    if (i < n) {
        int d = g_deg[i];
        v = d;
        g_dinv[i] = rsqrtf((float)(d + 1));
    }
    int x = v;
    #pragma unroll
    for (int o = 1; o < 32; o <<= 1) {
        int y = __shfl_up_sync(0xFFFFFFFFu, x, o);
        if ((tid & 31) >= o) x += y;
    }
    if ((tid & 31) == 31) warpsums[tid >> 5] = x;
    __syncthreads();
    if (tid < 32) {
        int w = warpsums[tid];
        #pragma unroll
        for (int o = 1; o < 32; o <<= 1) {
            int y = __shfl_up_sync(0xFFFFFFFFu, w, o);
            if (tid >= o) w += y;
        }
        warpsums[tid] = w;
    }
    __syncthreads();
    int incl = x + ((tid >= 32) ? warpsums[(tid >> 5) - 1] : 0);
    if (i < n) g_rowptr[i + 1] = incl;
    if (tid == 1023) g_bsum[b] = incl;
}

__global__ __launch_bounds__(1024) void k_scan23(int n, int nb) {
    __shared__ int w0s;
    __shared__ int s_off;
    int tid = threadIdx.x;
    int v = 0, x = 0;
    if (tid < 64) {
        v = (tid < nb) ? g_bsum[tid] : 0;
        x = v;
        #pragma unroll
        for (int o = 1; o < 32; o <<= 1) {
            int y = __shfl_up_sync(0xFFFFFFFFu, x, o);
            if ((tid & 31) >= o) x += y;
        }
        if (tid == 31) w0s = x;
    }
    __syncthreads();
    if (tid < 64) {
        int incl = x + ((tid >= 32) ? w0s : 0);
        if (tid == blockIdx.x) s_off = incl - v;
    }
    __syncthreads();
    int i = blockIdx.x * 1024 + tid;
    if (i < n) {
        int indeg = g_deg[i];
        int val = g_rowptr[i + 1] + s_off;
        g_rowptr[i + 1] = val;
        g_cursor[i] = val - indeg;
        g_deg[i] = 0;                               // reset for next replay
    }
    if (i == 0) g_rowptr[0] = 0;
}

__global__ void k_scatter(const int* __restrict__ ei, int e, int n) {
    int i = blockIdx.x * blockDim.x + threadIdx.x;
    if (i < e) {
        int s = ei[i], d = ei[e + i];
        if ((unsigned)d < (unsigned)n) {
            s = min(max(s, 0), n - 1);
            int pos = atomicAdd(&g_cursor[d], 1);
            g_col[pos] = s;
        }
    }
}

// ---------------- aggregation kernels (warp-per-node, 8 warps/block) ------------
__global__ __launch_bounds__(256) void k_aggX(int n) {
    int node = blockIdx.x * 8 + (threadIdx.x >> 5);
    int lane = threadIdx.x & 31;
    if (node >= n) return;
    const uint2* __restrict__ x2 = (const uint2*)g_xh;   // 32 uint2 per row
    float di = g_dinv[node];
    float acc[4], f[4];
    h4f(x2[(size_t)node * 32 + lane], f);
    #pragma unroll
    for (int j = 0; j < 4; j++) acc[j] = di * f[j];
    int e0 = g_rowptr[node], e1 = g_rowptr[node + 1];
    int e = e0;
    for (; e + 1 < e1; e += 2) {
        int s0 = g_col[e], s1 = g_col[e + 1];
        float d0 = g_dinv[s0], d1 = g_dinv[s1];
        float f0[4], f1[4];
        h4f(x2[(size_t)s0 * 32 + lane], f0);
        h4f(x2[(size_t)s1 * 32 + lane], f1);
        #pragma unroll
        for (int j = 0; j < 4; j++) acc[j] += d0 * f0[j] + d1 * f1[j];
    }
    if (e < e1) {
        int s = g_col[e];
        float d = g_dinv[s];
        h4f(x2[(size_t)s * 32 + lane], f);
        #pragma unroll
        for (int j = 0; j < 4; j++) acc[j] += d * f[j];
    }
    #pragma unroll
    for (int j = 0; j < 4; j++) acc[j] *= di;
    ((uint2*)g_aggxh)[(size_t)node * 32 + lane] = f4h(acc);
}

__global__ __launch_bounds__(256) void k_agg256(int n) {
    int node = blockIdx.x * 8 + (threadIdx.x >> 5);
    int lane = threadIdx.x & 31;
    if (node >= n) return;
    const uint4* __restrict__ m4 = (const uint4*)g_mh;   // 32 uint4 per row
    float sc[8], sh[8];
    {
        float4 s0 = ((const float4*)g_scale)[2 * lane];
        float4 s1 = ((const float4*)g_scale)[2 * lane + 1];
        float4 h0 = ((const float4*)g_shift)[2 * lane];
        float4 h1 = ((const float4*)g_shift)[2 * lane + 1];
        sc[0]=s0.x; sc[1]=s0.y; sc[2]=s0.z; sc[3]=s0.w;
        sc[4]=s1.x; sc[5]=s1.y; sc[6]=s1.z; sc[7]=s1.w;
        sh[0]=h0.x; sh[1]=h0.y; sh[2]=h0.z; sh[3]=h0.w;
        sh[4]=h1.x; sh[5]=h1.y; sh[6]=h1.z; sh[7]=h1.w;
    }
    float di = g_dinv[node];
    float acc[8], f[8];
    h8f(m4[(size_t)node * 32 + lane], f);
    #pragma unroll
    for (int j = 0; j < 8; j++)
        acc[j] = di * fmaxf(fmaf(f[j], sc[j], sh[j]), 0.f);
    int e0 = g_rowptr[node], e1 = g_rowptr[node + 1];
    int e = e0;
    for (; e + 1 < e1; e += 2) {
        int s0 = g_col[e], s1 = g_col[e + 1];
        float d0 = g_dinv[s0], d1 = g_dinv[s1];
        float f0[8], f1[8];
        h8f(m4[(size_t)s0 * 32 + lane], f0);
        h8f(m4[(size_t)s1 * 32 + lane], f1);
        #pragma unroll
        for (int j = 0; j < 8; j++)
            acc[j] += d0 * fmaxf(fmaf(f0[j], sc[j], sh[j]), 0.f)
                    + d1 * fmaxf(fmaf(f1[j], sc[j], sh[j]), 0.f);
    }
    if (e < e1) {
        int s = g_col[e];
        float d = g_dinv[s];
        h8f(m4[(size_t)s * 32 + lane], f);
        #pragma unroll
        for (int j = 0; j < 8; j++)
            acc[j] += d * fmaxf(fmaf(f[j], sc[j], sh[j]), 0.f);
    }
    #pragma unroll
    for (int j = 0; j < 8; j++) acc[j] *= di;
    ((uint4*)g_aggh)[(size_t)node * 32 + lane] = f8h(acc);
}

// ---------------- fp16 m16n8k16 MMA helper --------------------------------------
__device__ __forceinline__ void mma_f16(float c[4], const uint32_t a[4], const uint32_t b[2]) {
    asm volatile(
        "mma.sync.aligned.m16n8k16.row.col.f32.f16.f16.f32 "
        "{%0,%1,%2,%3}, {%4,%5,%6,%7}, {%8,%9}, {%0,%1,%2,%3};"
        : "+f"(c[0]), "+f"(c[1]), "+f"(c[2]), "+f"(c[3])
        : "r"(a[0]), "r"(a[1]), "r"(a[2]), "r"(a[3]), "r"(b[0]), "r"(b[1]));
}

#define TPAD 136    // B word stride: 136 % 32 == 8 -> conflict-free
#define ASTRIDE 20  // A word stride: {k*20 mod 32} covers all banks

// ---------------- fp16 TC GEMM (cp.async double-buffered) -----------------------
// C_h[M,256] = A_h[M,K] @ Wh[K,256] + bias ; BN stats fused.
template <int LAYER>
__global__ __launch_bounds__(256) void k_gemm256_tc(
    const float* __restrict__ bias, int M) {
    constexpr int K = (LAYER == 1) ? INF : HID;
    constexpr int NSTEP = K / 32;
    const __half* __restrict__ A = (LAYER == 1) ? g_aggxh : g_aggh;
    const uint32_t* __restrict__ Bw = (LAYER == 1) ? g_w1h : g_w2h;  // [K/2][256]
    __half* __restrict__ C = g_mh;

    __shared__ uint32_t As[2][128][ASTRIDE];  // [stage][m][k2] (16 of 20 used)
    __shared__ uint32_t Bs[2][16][TPAD];      // [stage][k2][n]
    __shared__ float s_s[128], s_s2[128];

    int t = threadIdx.x;
    int warp = t >> 5, lane = t & 31;
    int lr = lane >> 2, lc = lane & 3;
    int warpM = (warp >> 2) * 64;
    int warpN = (warp & 3) * 32;
    int rowBase = blockIdx.x * 128;
    int colBase = blockIdx.y * 128;

    if (t < 128) { s_s[t] = 0.f; s_s2[t] = 0.f; }

    float acc[4][4][4];
    #pragma unroll
    for (int mt = 0; mt < 4; mt++)
        #pragma unroll
        for (int nt = 0; nt < 4; nt++)
            #pragma unroll
            for (int j = 0; j < 4; j++) acc[mt][nt][j] = 0.f;

    auto load_stage = [&](int st, int kk) {
        #pragma unroll
        for (int h = 0; h < 2; h++) {
            int s = t + h * 256;
            int row = s >> 2;
            int c4 = (s & 3) << 2;                 // uint32 offset in row
            int r = min(rowBase + row, M - 1);     // clamp: dup rows, results unused
            cp16(&As[st][row][c4], A + (size_t)r * K + kk + (c4 << 1));
        }
        int kk2 = kk >> 1;
        #pragma unroll
        for (int h = 0; h < 2; h++) {
            int s = t + h * 256;
            int k2 = s >> 5;
            int n4 = (s & 31) << 2;
            cp16(&Bs[st][k2][n4], Bw + (size_t)(kk2 + k2) * 256 + colBase + n4);
        }
        asm volatile("cp.async.commit_group;");
    };

    load_stage(0, 0);
    #pragma unroll
    for (int i = 0; i < NSTEP; i++) {
        if (i + 1 < NSTEP) {
            load_stage((i + 1) & 1, (i + 1) * 32);
            asm volatile("cp.async.wait_group 1;");
        } else {
            asm volatile("cp.async.wait_group 0;");
        }
        __syncthreads();
        int st = i & 1;
        #pragma unroll
        for (int s = 0; s < 2; s++) {
            int kc2 = s * 8;
            uint32_t af[4][4], bf[4][2];
            #pragma unroll
            for (int nt = 0; nt < 4; nt++) {
                int nc = warpN + nt * 8 + lr;
                bf[nt][0] = Bs[st][kc2 + lc][nc];
                bf[nt][1] = Bs[st][kc2 + 4 + lc][nc];
            }
            #pragma unroll
            for (int mt = 0; mt < 4; mt++) {
                int m = warpM + mt * 16 + lr;
                af[mt][0] = As[st][m][kc2 + lc];
                af[mt][1] = As[st][m + 8][kc2 + lc];
                af[mt][2] = As[st][m][kc2 + 4 + lc];
                af[mt][3] = As[st][m + 8][kc2 + 4 + lc];
            }
            #pragma unroll
            for (int mt = 0; mt < 4; mt++)
                #pragma unroll
                for (int nt = 0; nt < 4; nt++)
                    mma_f16(acc[mt][nt], af[mt], bf[nt]);
        }
        __syncthreads();
    }

    // epilogue: bias add + half store + fused BN-stat accumulation (fp32)
    float ls[8], ls2[8];
    #pragma unroll
    for (int j = 0; j < 8; j++) { ls[j] = 0.f; ls2[j] = 0.f; }

    #pragma unroll
    for (int nt = 0; nt < 4; nt++) {
        int col = colBase + warpN + nt * 8 + 2 * lc;
        float b0 = bias[col], b1 = bias[col + 1];
        #pragma unroll
        for (int mt = 0; mt < 4; mt++) {
            int r0 = rowBase + warpM + mt * 16 + lr;
            if (r0 < M) {
                float o0 = acc[mt][nt][0] + b0, o1 = acc[mt][nt][1] + b1;
                *(__half2*)(C + (size_t)r0 * 256 + col) = __floats2half2_rn(o0, o1);
                ls[nt * 2]     += o0;  ls2[nt * 2]     = fmaf(o0, o0, ls2[nt * 2]);
                ls[nt * 2 + 1] += o1;  ls2[nt * 2 + 1] = fmaf(o1, o1, ls2[nt * 2 + 1]);
            }
            int r1 = r0 + 8;
            if (r1 < M) {
                float o2 = acc[mt][nt][2] + b0, o3 = acc[mt][nt][3] + b1;
                *(__half2*)(C + (size_t)r1 * 256 + col) = __floats2half2_rn(o2, o3);
                ls[nt * 2]     += o2;  ls2[nt * 2]     = fmaf(o2, o2, ls2[nt * 2]);
                ls[nt * 2 + 1] += o3;  ls2[nt * 2 + 1] = fmaf(o3, o3, ls2[nt * 2 + 1]);
            }
        }
    }
    __syncthreads();
    #pragma unroll
    for (int nt = 0; nt < 4; nt++) {
        int c0 = warpN + nt * 8 + 2 * lc;
        atomicAdd(&s_s[c0],      ls[nt * 2]);
        atomicAdd(&s_s2[c0],     ls2[nt * 2]);
        atomicAdd(&s_s[c0 + 1],  ls[nt * 2 + 1]);
        atomicAdd(&s_s2[c0 + 1], ls2[nt * 2 + 1]);
    }
    __syncthreads();
    if (t < 128) {
        atomicAdd(&g_sumf[colBase + t],  s_s[t]);
        atomicAdd(&g_sum2f[colBase + t], s_s2[t]);
    }
}

// ---------------- fp16 TC GEMM40: g_p3h[M,40] = dinv*(f2(g_mh) @ W3) ------------
__global__ __launch_bounds__(256) void k_gemm40_tc(int M) {
    const __half* __restrict__ A = g_mh;
    __shared__ uint32_t Bs2[128][OUTD];   // [k2][n] half2 {W[2k2],W[2k2+1]}
    __shared__ uint32_t As2[16][TPAD];    // [k2 within 32-k step][m]
    __shared__ float ssc[HID], ssh[HID];

    int t = threadIdx.x;
    int warp = t >> 5, lane = t & 31;
    int lr = lane >> 2, lc = lane & 3;
    int rowBase = blockIdx.x * 128;
    int warpM = warp * 16;

    ssc[t] = g_scale[t];
    ssh[t] = g_shift[t];
    for (int s = t; s < 128 * OUTD; s += 256)
        ((uint32_t*)Bs2)[ (s / OUTD) * OUTD + (s % OUTD) ] = g_w3h[s];
    __syncthreads();

    float acc[5][4];
    #pragma unroll
    for (int nt = 0; nt < 5; nt++)
        #pragma unroll
        for (int j = 0; j < 4; j++) acc[nt][j] = 0.f;

    for (int kk = 0; kk < HID; kk += 32) {
        // A fill with fused BN+ReLU, fp16 repack
        #pragma unroll
        for (int s = t; s < 512; s += 256) {
            int row = s >> 2;
            int k8 = (s & 3) << 3;
            int r = rowBase + row;
            float f[8] = {0.f, 0.f, 0.f, 0.f, 0.f, 0.f, 0.f, 0.f};
            if (r < M) {
                uint4 u = *(const uint4*)(A + (size_t)r * HID + kk + k8);
                h8f(u, f);
            }
            int c = kk + k8;
            #pragma unroll
            for (int j = 0; j < 8; j++)
                f[j] = fmaxf(fmaf(f[j], ssc[c + j], ssh[c + j]), 0.f);
            int k2 = k8 >> 1;
            As2[k2 + 0][row] = pack2h(f[0], f[1]);
            As2[k2 + 1][row] = pack2h(f[2], f[3]);
            As2[k2 + 2][row] = pack2h(f[4], f[5]);
            As2[k2 + 3][row] = pack2h(f[6], f[7]);
        }
        __syncthreads();

        int kk2 = kk >> 1;
        #pragma unroll
        for (int s = 0; s < 2; s++) {
            int kc2 = s * 8;
            uint32_t af[4];
            int m = warpM + lr;
            af[0] = As2[kc2 + lc][m];
            af[1] = As2[kc2 + lc][m + 8];
            af[2] = As2[kc2 + 4 + lc][m];
            af[3] = As2[kc2 + 4 + lc][m + 8];
            #pragma unroll
            for (int nt = 0; nt < 5; nt++) {
                int nc = nt * 8 + lr;
                uint32_t bf[2];
                bf[0] = Bs2[kk2 + kc2 + lc][nc];
                bf[1] = Bs2[kk2 + kc2 + 4 + lc][nc];
                mma_f16(acc[nt], af, bf);
            }
        }
        __syncthreads();
    }

    // epilogue: dinv scale, fp16 store
    int r0 = rowBase + warpM + lr;
    int r1 = r0 + 8;
    float d0 = (r0 < M) ? g_dinv[r0] : 0.f;
    float d1 = (r1 < M) ? g_dinv[r1] : 0.f;
    #pragma unroll
    for (int nt = 0; nt < 5; nt++) {
        int col = nt * 8 + 2 * lc;
        if (r0 < M)
            *(uint32_t*)(g_p3h + (size_t)r0 * OUTD + col) =
                pack2h(acc[nt][0] * d0, acc[nt][1] * d0);
        if (r1 < M)
            *(uint32_t*)(g_p3h + (size_t)r1 * OUTD + col) =
                pack2h(acc[nt][2] * d1, acc[nt][3] * d1);
    }
}

// ---------------- BN params from fused stats -----------------------------------
__global__ void k_bnparams(const float* __restrict__ g, const float* __restrict__ be, int n) {
    int t = threadIdx.x;  // 256
    float s = g_sumf[t], s2 = g_sum2f[t];
    g_sumf[t] = 0.f;
    g_sum2f[t] = 0.f;
    float inv_n = 1.f / (float)n;
    float mean = s * inv_n;
    float var  = fmaf(s2, inv_n, -mean * mean);
    float rs = rsqrtf(var + 1e-5f);
    float sc = rs * g[t];
    g_scale[t] = sc;
    g_shift[t] = be[t] - mean * sc;
}

// ---------------- fused: gather p3h + b3, then log_softmax(h3 @ Wl + bl) --------
__global__ void k_final40(const float* __restrict__ Wl, const float* __restrict__ bl,
                          const float* __restrict__ b3, float* __restrict__ out, int n) {
    __shared__ float sW[OUTD * OUTD];
    __shared__ float sb[OUTD], sb3[OUTD];
    int tid = threadIdx.x;  // 256
    for (int i = tid; i < OUTD * OUTD; i += 256) sW[i] = Wl[i];
    if (tid < OUTD) { sb[tid] = bl[tid]; sb3[tid] = b3[tid]; }
    __syncthreads();
    int warp = tid >> 5, lane = tid & 31;
    int node = blockIdx.x * 8 + warp;
    if (node >= n) return;

    // gather h3[node] (lanes 0..9 hold 4 values each)
    float a[4] = {0.f, 0.f, 0.f, 0.f};
    if (lane < 10) {
        const uint2* p2 = (const uint2*)g_p3h;   // 10 uint2 per row
        uint2 u = p2[(size_t)node * 10 + lane];
        h4f(u, a);
        int e0 = g_rowptr[node], e1 = g_rowptr[node + 1];
        for (int e = e0; e < e1; e++) {
            float f[4];
            h4f(p2[(size_t)g_col[e] * 10 + lane], f);
            a[0] += f[0]; a[1] += f[1]; a[2] += f[2]; a[3] += f[3];
        }
        float di = g_dinv[node];
        #pragma unroll
        for (int j = 0; j < 4; j++) a[j] = a[j] * di + sb3[lane * 4 + j];
    }

    // z = h3 @ Wl + bl (h3 redistributed via shfl)
    float z0 = sb[lane];
    float z1 = (lane < 8) ? sb[32 + lane] : -1e30f;
    #pragma unroll
    for (int k = 0; k < OUTD; k++) {
        float hk = __shfl_sync(0xFFFFFFFFu, a[k & 3], k >> 2);
        z0 = fmaf(hk, sW[k * OUTD + lane], z0);
        if (lane < 8) z1 = fmaf(hk, sW[k * OUTD + 32 + lane], z1);
    }
    float mx = fmaxf(z0, z1);
    #pragma unroll
    for (int o = 16; o; o >>= 1) mx = fmaxf(mx, __shfl_xor_sync(0xFFFFFFFFu, mx, o));
    float es = expf(z0 - mx) + ((lane < 8) ? expf(z1 - mx) : 0.f);
    #pragma unroll
    for (int o = 16; o; o >>= 1) es += __shfl_xor_sync(0xFFFFFFFFu, es, o);
    float L = mx + logf(es);
    out[(size_t)node * OUTD + lane] = z0 - L;
    if (lane < 8) out[(size_t)node * OUTD + 32 + lane] = z1 - L;
}

// ---------------- launch (kernel launches ONLY — no CUDA API calls) ------------
extern "C" void kernel_launch(void* const* d_in, const int* in_sizes, int n_in,
                              void* d_out, int out_size) {
    const float* x   = (const float*)d_in[0];
    const int*   ei  = (const int*)d_in[1];      // int32 edge_index (JAX default)
    const float* W1  = (const float*)d_in[2];
    const float* b1  = (const float*)d_in[3];
    const float* g1  = (const float*)d_in[4];
    const float* be1 = (const float*)d_in[5];
    const float* W2  = (const float*)d_in[6];
    const float* b2  = (const float*)d_in[7];
    const float* g2  = (const float*)d_in[8];
    const float* be2 = (const float*)d_in[9];
    const float* W3  = (const float*)d_in[10];
    const float* b3  = (const float*)d_in[11];
    const float* Wl  = (const float*)d_in[12];
    const float* bl  = (const float*)d_in[13];
    float* out = (float*)d_out;

    int n = in_sizes[0] / INF;     // 50000
    int e = in_sizes[1] / 2;       // 800000
    int nb = (n + 1023) / 1024;    // scan blocks (49)
    int total8 = n * INF / 8;      // 800000

    int prepN = (e > total8 ? e : total8);
    k_prep<<<(prepN + 255) / 256, 256>>>(ei, x, W1, W2, W3, e, n, total8);
    k_scan1<<<nb, 1024>>>(n);
    k_scan23<<<nb, 1024>>>(n, nb);
    k_scatter<<<(e + 255) / 256, 256>>>(ei, e, n);

    // layer 1: aggregate-first (width 128 fp16), then pipelined fp16 TC GEMM
    k_aggX<<<(n + 7) / 8, 256>>>(n);
    dim3 gg((n + 127) / 128, 2);
    k_gemm256_tc<1><<<gg, 256>>>(b1, n);
    k_bnparams<<<1, 256>>>(g1, be1, n);

    // layer 2: aggregate f1(m1) (width 256 fp16), then pipelined fp16 TC GEMM
    k_agg256<<<(n + 7) / 8, 256>>>(n);
    k_gemm256_tc<2><<<gg, 256>>>(b2, n);
    k_bnparams<<<1, 256>>>(g2, be2, n);

    // layer 3: fp16 TC GEMM (f2 fused into A-fill, dinv in epilogue)
    k_gemm40_tc<<<(n + 127) / 128, 256>>>(n);

    // fused width-40 aggregation + final linear + log_softmax
    k_final40<<<(n + 7) / 8, 256>>>(Wl, bl, b3, out, n);
}